// round 10
// baseline (speedup 1.0000x reference)
#include <cuda_runtime.h>
#include <cuda_bf16.h>
#include <math.h>

#define T_  4096
#define D_  768
#define H_  12
#define HD_ 64
#define FF_ 3072

// ---------------- scratch (device globals; no allocation allowed) ------------
__device__ __nv_bfloat16 g_hb  [T_ * D_];        // LN output (bf16, GEMM A)
__device__ float         g_qkv [3 * T_ * D_];    // head-major q|k|v fp32
__device__ __nv_bfloat16 g_ctxb[T_ * D_];        // attention out (bf16, GEMM A)
__device__ float         g_x2  [T_ * D_];        // residual after MHA
__device__ float         g_y1  [T_ * FF_];       // h@w1+b1 (fp32)
__device__ __nv_bfloat16 g_ffb [T_ * FF_];       // SwiGLU hidden (bf16, GEMM A)
// weights: bf16, transposed to [n][k]
__device__ __nv_bfloat16 g_Wqb[D_ * D_];
__device__ __nv_bfloat16 g_Wkb[D_ * D_];
__device__ __nv_bfloat16 g_Wvb[D_ * D_];
__device__ __nv_bfloat16 g_Wob[D_ * D_];
__device__ __nv_bfloat16 g_w1b[D_ * FF_];
__device__ __nv_bfloat16 g_w2b[D_ * FF_];
__device__ __nv_bfloat16 g_w3b[FF_ * D_];

// ---------------- fused weight convert+transpose: fp32 [K][N] -> bf16 [N][K] --
// One launch for all 7 weights. 32x32 tiles; flat block id decoded per-weight.
// Layout of flat id space:
//   [0,2304)      : Wq,Wk,Wv,Wo   (D x D;  576 tiles each)
//   [2304,6912)   : w1,w2         (K=D, N=FF; 2304 tiles each)
//   [6912,9216)   : w3            (K=FF, N=D; 2304 tiles)
__global__ void wconv_all_kernel(const float* __restrict__ Wq, const float* __restrict__ Wk,
                                 const float* __restrict__ Wv, const float* __restrict__ Wo,
                                 const float* __restrict__ w1, const float* __restrict__ w2,
                                 const float* __restrict__ w3) {
    __shared__ float tile[32][33];
    int fb = blockIdx.x;
    const float* W; __nv_bfloat16* out; int K, N, t;
    if (fb < 2304) {
        int wi = fb / 576; t = fb % 576; K = D_; N = D_;
        W   = (wi == 0) ? Wq : (wi == 1) ? Wk : (wi == 2) ? Wv : Wo;
        out = (wi == 0) ? g_Wqb : (wi == 1) ? g_Wkb : (wi == 2) ? g_Wvb : g_Wob;
    } else if (fb < 6912) {
        int wi = (fb - 2304) / 2304; t = (fb - 2304) % 2304; K = D_; N = FF_;
        W   = (wi == 0) ? w1 : w2;
        out = (wi == 0) ? g_w1b : g_w2b;
    } else {
        t = fb - 6912; K = FF_; N = D_;
        W = w3; out = g_w3b;
    }
    int ntiles = N / 32;
    int n0 = (t % ntiles) * 32, k0 = (t / ntiles) * 32;
    int tx = threadIdx.x, ty = threadIdx.y;   // 32 x 8
    #pragma unroll
    for (int e = 0; e < 4; e++)
        tile[ty + e * 8][tx] = W[(size_t)(k0 + ty + e * 8) * N + n0 + tx];
    __syncthreads();
    #pragma unroll
    for (int e = 0; e < 4; e++)
        out[(size_t)(n0 + ty + e * 8) * K + k0 + tx] = __float2bfloat16(tile[tx][ty + e * 8]);
}

// ---------------- LayerNorm (bf16 output) ------------------------------------
__global__ void ln_kernel(const float* __restrict__ x, const float* __restrict__ g,
                          const float* __restrict__ s, __nv_bfloat16* __restrict__ out) {
    int row = blockIdx.x;
    const float* xr = x + (size_t)row * D_;
    float sum = 0.f, sq = 0.f;
    for (int i = threadIdx.x; i < D_; i += 256) {
        float v = xr[i]; sum += v; sq += v * v;
    }
    __shared__ float ssum[8], ssq[8];
    #pragma unroll
    for (int o = 16; o > 0; o >>= 1) {
        sum += __shfl_down_sync(0xffffffffu, sum, o);
        sq  += __shfl_down_sync(0xffffffffu, sq,  o);
    }
    int w = threadIdx.x >> 5, l = threadIdx.x & 31;
    if (l == 0) { ssum[w] = sum; ssq[w] = sq; }
    __syncthreads();
    if (threadIdx.x == 0) {
        float a = 0.f, b = 0.f;
        #pragma unroll
        for (int i = 0; i < 8; i++) { a += ssum[i]; b += ssq[i]; }
        ssum[0] = a; ssq[0] = b;
    }
    __syncthreads();
    float mean = ssum[0] * (1.f / D_);
    float var  = ssq[0]  * (1.f / D_) - mean * mean;
    float rstd = rsqrtf(var + 1e-5f);
    for (int i = threadIdx.x; i < D_; i += 256)
        out[(size_t)row * D_ + i] = __float2bfloat16(g[i] * (xr[i] - mean) * rstd + s[i]);
}

// ---------------- helpers ------------------------------------------------------
__device__ __forceinline__ unsigned cvt_tf32(float x) {
    unsigned r;
    asm("cvt.rna.tf32.f32 %0, %1;" : "=r"(r) : "f"(x));
    return r;
}

#define MMA_TF32(acc, a0, a1, a2, a3, b0, b1)                                   \
    asm volatile(                                                               \
        "mma.sync.aligned.m16n8k8.row.col.f32.tf32.tf32.f32 "                   \
        "{%0,%1,%2,%3}, {%4,%5,%6,%7}, {%8,%9}, {%0,%1,%2,%3};"                 \
        : "+f"((acc)[0]), "+f"((acc)[1]), "+f"((acc)[2]), "+f"((acc)[3])        \
        : "r"(a0), "r"(a1), "r"(a2), "r"(a3), "r"(b0), "r"(b1))

#define MMA_BF16(acc, a0, a1, a2, a3, b0, b1)                                   \
    asm volatile(                                                               \
        "mma.sync.aligned.m16n8k16.row.col.f32.bf16.bf16.f32 "                  \
        "{%0,%1,%2,%3}, {%4,%5,%6,%7}, {%8,%9}, {%0,%1,%2,%3};"                 \
        : "+f"((acc)[0]), "+f"((acc)[1]), "+f"((acc)[2]), "+f"((acc)[3])        \
        : "r"(a0), "r"(a1), "r"(a2), "r"(a3), "r"(b0), "r"(b1))

#define LDSM_X4(r0, r1, r2, r3, addr)                                           \
    asm volatile("ldmatrix.sync.aligned.m8n8.x4.shared.b16 {%0,%1,%2,%3}, [%4];" \
        : "=r"(r0), "=r"(r1), "=r"(r2), "=r"(r3) : "r"(addr))

// ---------------- bf16 tensor-core GEMM --------------------------------------
// C[M,N] = A[M,K] @ Bt[N,K]^T. 128x128x32 CTA tile, 8 warps (2x4), warp tile
// 64x32, mma.m16n8k16.bf16 fp32-accum. Fragments via ldmatrix.x4 (pitch 40
// bf16 = 20 words -> every 8-row phase covers all 32 banks; conflict-free).
#define BM 128
#define BN 128
#define HKB 32      // bf16 k per tile
#define HP  40      // smem pitch in bf16

enum { EP_HEAD = 0, EP_BIASRES = 1, EP_BIAS = 2, EP_SWIGLU = 3 };

template <int MODE>
__global__ void __launch_bounds__(256, 2) bf16_gemm(
    const __nv_bfloat16* __restrict__ A,  const __nv_bfloat16* __restrict__ B,
    const __nv_bfloat16* __restrict__ B1, const __nv_bfloat16* __restrict__ B2,
    const float* __restrict__ bias, const float* __restrict__ res,
    const float* __restrict__ aux,  float* __restrict__ C,
    __nv_bfloat16* __restrict__ Cb, int N, int K)
{
    if (MODE == EP_HEAD) {      // grid.z selects q/k/v weight + output slab
        if (blockIdx.z == 1)      { B = B1; C += (size_t)T_ * D_; }
        else if (blockIdx.z == 2) { B = B2; C += (size_t)2 * T_ * D_; }
    }
    __shared__ __nv_bfloat16 As[2][BM][HP];
    __shared__ __nv_bfloat16 Bs[2][BN][HP];
    int tid = threadIdx.x;
    int warp = tid >> 5, lane = tid & 31;
    int g = lane >> 2, tg = lane & 3;
    int wm = warp >> 2, wn = warp & 3;
    int m0 = blockIdx.y * BM, n0 = blockIdx.x * BN;

    // ldmatrix lane addressing (constant per thread)
    int a_row = (lane & 15), a_colh = (lane >> 4) * 8;          // A: rows 0..15, col half
    int b_row = (lane & 7) + ((lane >> 4) << 3);                // B: row within 16-pair
    int b_colh = ((lane >> 3) & 1) * 8;

    float acc[4][4][4] = {};
    int nk = K / HKB;

    #define CPA(buf, kt) do {                                                   \
        int k0_ = (kt) * HKB;                                                   \
        _Pragma("unroll")                                                       \
        for (int e = 0; e < 2; e++) {                                           \
            int idx = tid + e * 256;                                            \
            int r_ = idx >> 2, c_ = (idx & 3) * 8;                              \
            const __nv_bfloat16* src_ = A + (size_t)(m0 + r_) * K + k0_ + c_;   \
            unsigned dst_ = (unsigned)__cvta_generic_to_shared(&As[buf][r_][c_]); \
            asm volatile("cp.async.cg.shared.global [%0], [%1], 16;\n"          \
                         :: "r"(dst_), "l"(src_));                              \
        }                                                                       \
    } while (0)
    #define CPB(buf, kt) do {                                                   \
        int k0_ = (kt) * HKB;                                                   \
        _Pragma("unroll")                                                       \
        for (int e = 0; e < 2; e++) {                                           \
            int idx = tid + e * 256;                                            \
            int r_ = idx >> 2, c_ = (idx & 3) * 8;                              \
            const __nv_bfloat16* src_ = B + (size_t)(n0 + r_) * K + k0_ + c_;   \
            unsigned dst_ = (unsigned)__cvta_generic_to_shared(&Bs[buf][r_][c_]); \
            asm volatile("cp.async.cg.shared.global [%0], [%1], 16;\n"          \
                         :: "r"(dst_), "l"(src_));                              \
        }                                                                       \
    } while (0)

    CPA(0, 0); CPB(0, 0);
    asm volatile("cp.async.commit_group;\n");

    for (int t = 0; t < nk; t++) {
        int buf = t & 1;
        if (t + 1 < nk) {
            CPA(buf ^ 1, t + 1); CPB(buf ^ 1, t + 1);
            asm volatile("cp.async.commit_group;\n");
            asm volatile("cp.async.wait_group 1;\n");
        } else {
            asm volatile("cp.async.wait_group 0;\n");
        }
        __syncthreads();

        #pragma unroll
        for (int ks = 0; ks < 2; ks++) {
            int kb = ks * 16;
            unsigned af[4][4], bfr[4][2];
            #pragma unroll
            for (int i = 0; i < 4; i++) {
                unsigned addr = (unsigned)__cvta_generic_to_shared(
                    &As[buf][wm * 64 + i * 16 + a_row][kb + a_colh]);
                LDSM_X4(af[i][0], af[i][1], af[i][2], af[i][3], addr);
            }
            #pragma unroll
            for (int jp = 0; jp < 2; jp++) {
                unsigned addr = (unsigned)__cvta_generic_to_shared(
                    &Bs[buf][wn * 32 + jp * 16 + b_row][kb + b_colh]);
                LDSM_X4(bfr[2 * jp][0], bfr[2 * jp][1],
                        bfr[2 * jp + 1][0], bfr[2 * jp + 1][1], addr);
            }
            #pragma unroll
            for (int i = 0; i < 4; i++)
                #pragma unroll
                for (int j = 0; j < 4; j++)
                    MMA_BF16(acc[i][j], af[i][0], af[i][1], af[i][2], af[i][3],
                             bfr[j][0], bfr[j][1]);
        }
        __syncthreads();
    }

    // --- epilogue ---
    #pragma unroll
    for (int i = 0; i < 4; i++) {
        int rbase = m0 + wm * 64 + i * 16 + g;
        #pragma unroll
        for (int j = 0; j < 4; j++) {
            int cbase = n0 + wn * 32 + j * 8 + tg * 2;
            #pragma unroll
            for (int hh = 0; hh < 2; hh++) {
                int rr = rbase + hh * 8;
                #pragma unroll
                for (int cc = 0; cc < 2; cc++) {
                    int nn = cbase + cc;
                    float v = acc[i][j][hh * 2 + cc];
                    if (MODE == EP_HEAD) {
                        C[(size_t)((nn >> 6) * T_ + rr) * 64 + (nn & 63)] = v;
                    } else if (MODE == EP_BIASRES) {
                        C[(size_t)rr * N + nn] = v + bias[nn] + res[(size_t)rr * N + nn];
                    } else if (MODE == EP_BIAS) {
                        C[(size_t)rr * N + nn] = v + bias[nn];
                    } else { // EP_SWIGLU
                        float a = aux[(size_t)rr * N + nn];
                        float sig = 1.f / (1.f + __expf(-a));
                        Cb[(size_t)rr * N + nn] = __float2bfloat16((a * sig) * (v + bias[nn]));
                    }
                }
            }
        }
    }
    #undef CPA
    #undef CPB
}

// ---------------- causal flash attention, tf32 MMA ---------------------------
#define FAP 68

__global__ void __launch_bounds__(256) attn_mma_kernel(
    const float* __restrict__ q, const float* __restrict__ k,
    const float* __restrict__ v, __nv_bfloat16* __restrict__ ctx)
{
    extern __shared__ float sm[];
    float* Ks = sm;
    float* Vs = Ks + 64 * FAP;
    float* Ps = Vs + 64 * FAP;

    int tid = threadIdx.x;
    int warp = tid >> 5, lane = tid & 31;
    int g = lane >> 2, tg = lane & 3;
    int qt = gridDim.x - 1 - blockIdx.x;
    int h = blockIdx.y;
    int qm0 = qt * 128;
    const float* qh = q + (size_t)h * (T_ * HD_);
    const float* kh = k + (size_t)h * (T_ * HD_);
    const float* vh = v + (size_t)h * (T_ * HD_);

    int r0 = qm0 + warp * 16 + g;
    int r1 = r0 + 8;

    unsigned qf[8][4];
    #pragma unroll
    for (int kc = 0; kc < 8; kc++) {
        qf[kc][0] = cvt_tf32(qh[(size_t)r0 * 64 + kc * 8 + tg    ] * 0.125f);
        qf[kc][1] = cvt_tf32(qh[(size_t)r1 * 64 + kc * 8 + tg    ] * 0.125f);
        qf[kc][2] = cvt_tf32(qh[(size_t)r0 * 64 + kc * 8 + tg + 4] * 0.125f);
        qf[kc][3] = cvt_tf32(qh[(size_t)r1 * 64 + kc * 8 + tg + 4] * 0.125f);
    }

    float oacc[8][4] = {};
    float m0 = -1e30f, m1 = -1e30f, l0 = 0.f, l1 = 0.f;
    int nkt = 2 * qt + 2;

    for (int kt = 0; kt < nkt; kt++) {
        int km0 = kt * 64;
        __syncthreads();
        #pragma unroll
        for (int e = 0; e < 4; e++) {
            int idx = tid + e * 256;
            int r = idx >> 4, d4 = (idx & 15) * 4;
            *(float4*)&Ks[r * FAP + d4] = *(const float4*)&kh[(size_t)(km0 + r) * 64 + d4];
            *(float4*)&Vs[r * FAP + d4] = *(const float4*)&vh[(size_t)(km0 + r) * 64 + d4];
        }
        __syncthreads();

        float sacc[8][4] = {};
        #pragma unroll
        for (int kc = 0; kc < 8; kc++) {
            #pragma unroll
            for (int j = 0; j < 8; j++) {
                unsigned b0 = cvt_tf32(Ks[(j * 8 + g) * FAP + kc * 8 + tg    ]);
                unsigned b1 = cvt_tf32(Ks[(j * 8 + g) * FAP + kc * 8 + tg + 4]);
                MMA_TF32(sacc[j], qf[kc][0], qf[kc][1], qf[kc][2], qf[kc][3], b0, b1);
            }
        }

        if (km0 + 63 > qm0 + warp * 16) {
            #pragma unroll
            for (int j = 0; j < 8; j++) {
                int c0 = km0 + j * 8 + tg * 2, c1 = c0 + 1;
                if (c0 > r0) sacc[j][0] = -1e30f;
                if (c1 > r0) sacc[j][1] = -1e30f;
                if (c0 > r1) sacc[j][2] = -1e30f;
                if (c1 > r1) sacc[j][3] = -1e30f;
            }
        }

        float t0 = -1e30f, t1 = -1e30f;
        #pragma unroll
        for (int j = 0; j < 8; j++) {
            t0 = fmaxf(t0, fmaxf(sacc[j][0], sacc[j][1]));
            t1 = fmaxf(t1, fmaxf(sacc[j][2], sacc[j][3]));
        }
        t0 = fmaxf(t0, __shfl_xor_sync(0xffffffffu, t0, 1));
        t0 = fmaxf(t0, __shfl_xor_sync(0xffffffffu, t0, 2));
        t1 = fmaxf(t1, __shfl_xor_sync(0xffffffffu, t1, 1));
        t1 = fmaxf(t1, __shfl_xor_sync(0xffffffffu, t1, 2));
        float nm0 = fmaxf(m0, t0), nm1 = fmaxf(m1, t1);
        float rs0 = __expf(m0 - nm0), rs1 = __expf(m1 - nm1);
        m0 = nm0; m1 = nm1;

        int pr0 = (warp * 16 + g) * FAP, pr1 = pr0 + 8 * FAP;
        float sum0 = 0.f, sum1 = 0.f;
        #pragma unroll
        for (int j = 0; j < 8; j++) {
            float p00 = __expf(sacc[j][0] - m0);
            float p01 = __expf(sacc[j][1] - m0);
            float p10 = __expf(sacc[j][2] - m1);
            float p11 = __expf(sacc[j][3] - m1);
            sum0 += p00 + p01; sum1 += p10 + p11;
            int c = j * 8 + tg * 2;
            Ps[pr0 + c] = p00; Ps[pr0 + c + 1] = p01;
            Ps[pr1 + c] = p10; Ps[pr1 + c + 1] = p11;
        }
        l0 = l0 * rs0 + sum0;
        l1 = l1 * rs1 + sum1;
        #pragma unroll
        for (int j = 0; j < 8; j++) {
            oacc[j][0] *= rs0; oacc[j][1] *= rs0;
            oacc[j][2] *= rs1; oacc[j][3] *= rs1;
        }
        __syncwarp();

        #pragma unroll
        for (int kc = 0; kc < 8; kc++) {
            unsigned a0 = cvt_tf32(Ps[pr0 + kc * 8 + tg    ]);
            unsigned a1 = cvt_tf32(Ps[pr1 + kc * 8 + tg    ]);
            unsigned a2 = cvt_tf32(Ps[pr0 + kc * 8 + tg + 4]);
            unsigned a3 = cvt_tf32(Ps[pr1 + kc * 8 + tg + 4]);
            #pragma unroll
            for (int j = 0; j < 8; j++) {
                unsigned b0 = cvt_tf32(Vs[(kc * 8 + tg    ) * FAP + j * 8 + g]);
                unsigned b1 = cvt_tf32(Vs[(kc * 8 + tg + 4) * FAP + j * 8 + g]);
                MMA_TF32(oacc[j], a0, a1, a2, a3, b0, b1);
            }
        }
        __syncwarp();
    }

    l0 += __shfl_xor_sync(0xffffffffu, l0, 1);
    l0 += __shfl_xor_sync(0xffffffffu, l0, 2);
    l1 += __shfl_xor_sync(0xffffffffu, l1, 1);
    l1 += __shfl_xor_sync(0xffffffffu, l1, 2);
    float inv0 = 1.f / l0, inv1 = 1.f / l1;
    #pragma unroll
    for (int j = 0; j < 8; j++) {
        int col = h * 64 + j * 8 + tg * 2;
        ctx[(size_t)r0 * D_ + col    ] = __float2bfloat16(oacc[j][0] * inv0);
        ctx[(size_t)r0 * D_ + col + 1] = __float2bfloat16(oacc[j][1] * inv0);
        ctx[(size_t)r1 * D_ + col    ] = __float2bfloat16(oacc[j][2] * inv1);
        ctx[(size_t)r1 * D_ + col + 1] = __float2bfloat16(oacc[j][3] * inv1);
    }
}

// ---------------- launch -----------------------------------------------------
extern "C" void kernel_launch(void* const* d_in, const int* in_sizes, int n_in,
                              void* d_out, int out_size) {
    const float* x  = (const float*)d_in[0];
    const float* Wq = (const float*)d_in[1];
    const float* Wk = (const float*)d_in[2];
    const float* Wv = (const float*)d_in[3];
    const float* Wo = (const float*)d_in[4];
    const float* bo = (const float*)d_in[5];
    const float* w1 = (const float*)d_in[6];
    const float* b1 = (const float*)d_in[7];
    const float* w2 = (const float*)d_in[8];
    const float* b2 = (const float*)d_in[9];
    const float* w3 = (const float*)d_in[10];
    const float* b3 = (const float*)d_in[11];
    const float* g1 = (const float*)d_in[12];
    const float* s1 = (const float*)d_in[13];
    const float* g2 = (const float*)d_in[14];
    const float* s2 = (const float*)d_in[15];
    float* out = (float*)d_out;

    __nv_bfloat16 *hb, *ctxb, *ffb, *Wqb, *Wkb, *Wvb, *Wob, *w1b, *w2b, *w3b;
    float *qkvb, *x2b, *y1b;
    cudaGetSymbolAddress((void**)&hb,   g_hb);
    cudaGetSymbolAddress((void**)&qkvb, g_qkv);
    cudaGetSymbolAddress((void**)&ctxb, g_ctxb);
    cudaGetSymbolAddress((void**)&x2b,  g_x2);
    cudaGetSymbolAddress((void**)&y1b,  g_y1);
    cudaGetSymbolAddress((void**)&ffb,  g_ffb);
    cudaGetSymbolAddress((void**)&Wqb,  g_Wqb);
    cudaGetSymbolAddress((void**)&Wkb,  g_Wkb);
    cudaGetSymbolAddress((void**)&Wvb,  g_Wvb);
    cudaGetSymbolAddress((void**)&Wob,  g_Wob);
    cudaGetSymbolAddress((void**)&w1b,  g_w1b);
    cudaGetSymbolAddress((void**)&w2b,  g_w2b);
    cudaGetSymbolAddress((void**)&w3b,  g_w3b);

    const int attn_smem = (64 * FAP + 64 * FAP + 128 * FAP) * (int)sizeof(float);
    cudaFuncSetAttribute(attn_mma_kernel, cudaFuncAttributeMaxDynamicSharedMemorySize, attn_smem);

    // weight prepass: all 7 conversions in ONE launch
    wconv_all_kernel<<<9216, dim3(32, 8)>>>(Wq, Wk, Wv, Wo, w1, w2, w3);

    dim3 gD(D_ / BN, T_ / BM);        // (6, 32)
    dim3 gQKV(D_ / BN, T_ / BM, 3);   // fused QKV
    dim3 gF(FF_ / BN, T_ / BM);       // (24, 32)

    // 1. LN1 (bf16 out)
    ln_kernel<<<T_, 256>>>(x, g1, s1, hb);
    // 2. fused QKV projections (head-major fp32 out)
    bf16_gemm<EP_HEAD><<<gQKV, 256>>>(hb, Wqb, Wkb, Wvb, nullptr, nullptr, nullptr,
                                      qkvb, nullptr, D_, D_);
    // 3. causal attention (tf32 MMA; bf16 ctx out)
    attn_mma_kernel<<<dim3(T_ / 128, H_), 256, attn_smem>>>(
        qkvb, qkvb + (size_t)T_ * D_, qkvb + (size_t)2 * T_ * D_, ctxb);
    // 4. out projection + bias + residual (fp32 out)
    bf16_gemm<EP_BIASRES><<<gD, 256>>>(ctxb, Wob, nullptr, nullptr, bo, x, nullptr,
                                       x2b, nullptr, D_, D_);
    // 5. LN2 (bf16 out)
    ln_kernel<<<T_, 256>>>(x2b, g2, s2, hb);
    // 6. SwiGLU: y1 = h@w1+b1 (fp32) ; ff = silu(y1) * (h@w2+b2) (bf16)
    bf16_gemm<EP_BIAS>  <<<gF, 256>>>(hb, w1b, nullptr, nullptr, b1, nullptr, nullptr,
                                      y1b, nullptr, FF_, D_);
    bf16_gemm<EP_SWIGLU><<<gF, 256>>>(hb, w2b, nullptr, nullptr, b2, nullptr, y1b,
                                      nullptr, ffb, FF_, D_);
    // 7. down projection + bias + residual -> output (fp32)
    bf16_gemm<EP_BIASRES><<<gD, 256>>>(ffb, w3b, nullptr, nullptr, b3, x2b, nullptr,
                                       out, nullptr, D_, FF_);
}

// round 11
// speedup vs baseline: 1.5822x; 1.5822x over previous
#include <cuda_runtime.h>
#include <cuda_bf16.h>
#include <math.h>

#define T_  4096
#define D_  768
#define H_  12
#define HD_ 64
#define FF_ 3072

// ---------------- scratch (device globals; no allocation allowed) ------------
__device__ __nv_bfloat16 g_hb  [T_ * D_];        // LN output (bf16, GEMM A)
__device__ float         g_qkv [3 * T_ * D_];    // head-major q|k|v (k,v = tf32 bits)
__device__ __nv_bfloat16 g_ctxb[T_ * D_];        // attention out (bf16, GEMM A)
__device__ float         g_x2  [T_ * D_];        // residual after MHA
__device__ float         g_y1  [T_ * FF_];       // h@w1+b1 (fp32)
__device__ __nv_bfloat16 g_ffb [T_ * FF_];       // SwiGLU hidden (bf16, GEMM A)
// weights: bf16, transposed to [n][k]
__device__ __nv_bfloat16 g_Wqb[D_ * D_];
__device__ __nv_bfloat16 g_Wkb[D_ * D_];
__device__ __nv_bfloat16 g_Wvb[D_ * D_];
__device__ __nv_bfloat16 g_Wob[D_ * D_];
__device__ __nv_bfloat16 g_w1b[D_ * FF_];
__device__ __nv_bfloat16 g_w2b[D_ * FF_];
__device__ __nv_bfloat16 g_w3b[FF_ * D_];

// ---------------- fused weight convert+transpose: fp32 [K][N] -> bf16 [N][K] --
__global__ void wconv_all_kernel(const float* __restrict__ Wq, const float* __restrict__ Wk,
                                 const float* __restrict__ Wv, const float* __restrict__ Wo,
                                 const float* __restrict__ w1, const float* __restrict__ w2,
                                 const float* __restrict__ w3) {
    __shared__ float tile[32][33];
    int fb = blockIdx.x;
    const float* W; __nv_bfloat16* out; int K, N, t;
    if (fb < 2304) {
        int wi = fb / 576; t = fb % 576; K = D_; N = D_;
        W   = (wi == 0) ? Wq : (wi == 1) ? Wk : (wi == 2) ? Wv : Wo;
        out = (wi == 0) ? g_Wqb : (wi == 1) ? g_Wkb : (wi == 2) ? g_Wvb : g_Wob;
    } else if (fb < 6912) {
        int wi = (fb - 2304) / 2304; t = (fb - 2304) % 2304; K = D_; N = FF_;
        W   = (wi == 0) ? w1 : w2;
        out = (wi == 0) ? g_w1b : g_w2b;
    } else {
        t = fb - 6912; K = FF_; N = D_;
        W = w3; out = g_w3b;
    }
    int ntiles = N / 32;
    int n0 = (t % ntiles) * 32, k0 = (t / ntiles) * 32;
    int tx = threadIdx.x, ty = threadIdx.y;   // 32 x 8
    #pragma unroll
    for (int e = 0; e < 4; e++)
        tile[ty + e * 8][tx] = W[(size_t)(k0 + ty + e * 8) * N + n0 + tx];
    __syncthreads();
    #pragma unroll
    for (int e = 0; e < 4; e++)
        out[(size_t)(n0 + ty + e * 8) * K + k0 + tx] = __float2bfloat16(tile[tx][ty + e * 8]);
}

// ---------------- LayerNorm (bf16 output) ------------------------------------
__global__ void ln_kernel(const float* __restrict__ x, const float* __restrict__ g,
                          const float* __restrict__ s, __nv_bfloat16* __restrict__ out) {
    int row = blockIdx.x;
    const float* xr = x + (size_t)row * D_;
    float sum = 0.f, sq = 0.f;
    for (int i = threadIdx.x; i < D_; i += 256) {
        float v = xr[i]; sum += v; sq += v * v;
    }
    __shared__ float ssum[8], ssq[8];
    #pragma unroll
    for (int o = 16; o > 0; o >>= 1) {
        sum += __shfl_down_sync(0xffffffffu, sum, o);
        sq  += __shfl_down_sync(0xffffffffu, sq,  o);
    }
    int w = threadIdx.x >> 5, l = threadIdx.x & 31;
    if (l == 0) { ssum[w] = sum; ssq[w] = sq; }
    __syncthreads();
    if (threadIdx.x == 0) {
        float a = 0.f, b = 0.f;
        #pragma unroll
        for (int i = 0; i < 8; i++) { a += ssum[i]; b += ssq[i]; }
        ssum[0] = a; ssq[0] = b;
    }
    __syncthreads();
    float mean = ssum[0] * (1.f / D_);
    float var  = ssq[0]  * (1.f / D_) - mean * mean;
    float rstd = rsqrtf(var + 1e-5f);
    for (int i = threadIdx.x; i < D_; i += 256)
        out[(size_t)row * D_ + i] = __float2bfloat16(g[i] * (xr[i] - mean) * rstd + s[i]);
}

// ---------------- helpers ------------------------------------------------------
__device__ __forceinline__ unsigned cvt_tf32(float x) {
    unsigned r;
    asm("cvt.rna.tf32.f32 %0, %1;" : "=r"(r) : "f"(x));
    return r;
}

#define MMA_TF32(acc, a0, a1, a2, a3, b0, b1)                                   \
    asm volatile(                                                               \
        "mma.sync.aligned.m16n8k8.row.col.f32.tf32.tf32.f32 "                   \
        "{%0,%1,%2,%3}, {%4,%5,%6,%7}, {%8,%9}, {%0,%1,%2,%3};"                 \
        : "+f"((acc)[0]), "+f"((acc)[1]), "+f"((acc)[2]), "+f"((acc)[3])        \
        : "r"(a0), "r"(a1), "r"(a2), "r"(a3), "r"(b0), "r"(b1))

#define MMA_BF16(acc, a0, a1, a2, a3, b0, b1)                                   \
    asm volatile(                                                               \
        "mma.sync.aligned.m16n8k16.row.col.f32.bf16.bf16.f32 "                  \
        "{%0,%1,%2,%3}, {%4,%5,%6,%7}, {%8,%9}, {%0,%1,%2,%3};"                 \
        : "+f"((acc)[0]), "+f"((acc)[1]), "+f"((acc)[2]), "+f"((acc)[3])        \
        : "r"(a0), "r"(a1), "r"(a2), "r"(a3), "r"(b0), "r"(b1))

// ---------------- bf16 tensor-core GEMM (R9 scalar-LDS inner loop) ------------
#define BM 128
#define BN 128
#define HKB 32      // bf16 k per tile
#define HP  40      // smem pitch in bf16

enum { EP_HEAD = 0, EP_BIASRES = 1, EP_BIAS = 2, EP_SWIGLU = 3 };

template <int MODE>
__global__ void __launch_bounds__(256, 2) bf16_gemm(
    const __nv_bfloat16* __restrict__ A,  const __nv_bfloat16* __restrict__ B,
    const __nv_bfloat16* __restrict__ B1, const __nv_bfloat16* __restrict__ B2,
    const float* __restrict__ bias, const float* __restrict__ res,
    const float* __restrict__ aux,  float* __restrict__ C,
    __nv_bfloat16* __restrict__ Cb, int N, int K)
{
    int slab = 0;
    if (MODE == EP_HEAD) {      // grid.z selects q/k/v weight + output slab
        slab = blockIdx.z;
        if (slab == 1)      { B = B1; C += (size_t)T_ * D_; }
        else if (slab == 2) { B = B2; C += (size_t)2 * T_ * D_; }
    }
    __shared__ __nv_bfloat16 As[2][BM][HP];
    __shared__ __nv_bfloat16 Bs[2][BN][HP];
    int tid = threadIdx.x;
    int warp = tid >> 5, lane = tid & 31;
    int g = lane >> 2, tg = lane & 3;
    int wm = warp >> 2, wn = warp & 3;
    int m0 = blockIdx.y * BM, n0 = blockIdx.x * BN;

    float acc[4][4][4] = {};
    int nk = K / HKB;

    #define CPA(buf, kt) do {                                                   \
        int k0_ = (kt) * HKB;                                                   \
        _Pragma("unroll")                                                       \
        for (int e = 0; e < 2; e++) {                                           \
            int idx = tid + e * 256;                                            \
            int r_ = idx >> 2, c_ = (idx & 3) * 8;                              \
            const __nv_bfloat16* src_ = A + (size_t)(m0 + r_) * K + k0_ + c_;   \
            unsigned dst_ = (unsigned)__cvta_generic_to_shared(&As[buf][r_][c_]); \
            asm volatile("cp.async.cg.shared.global [%0], [%1], 16;\n"          \
                         :: "r"(dst_), "l"(src_));                              \
        }                                                                       \
    } while (0)
    #define CPB(buf, kt) do {                                                   \
        int k0_ = (kt) * HKB;                                                   \
        _Pragma("unroll")                                                       \
        for (int e = 0; e < 2; e++) {                                           \
            int idx = tid + e * 256;                                            \
            int r_ = idx >> 2, c_ = (idx & 3) * 8;                              \
            const __nv_bfloat16* src_ = B + (size_t)(n0 + r_) * K + k0_ + c_;   \
            unsigned dst_ = (unsigned)__cvta_generic_to_shared(&Bs[buf][r_][c_]); \
            asm volatile("cp.async.cg.shared.global [%0], [%1], 16;\n"          \
                         :: "r"(dst_), "l"(src_));                              \
        }                                                                       \
    } while (0)

    CPA(0, 0); CPB(0, 0);
    asm volatile("cp.async.commit_group;\n");

    for (int t = 0; t < nk; t++) {
        int buf = t & 1;
        if (t + 1 < nk) {
            CPA(buf ^ 1, t + 1); CPB(buf ^ 1, t + 1);
            asm volatile("cp.async.commit_group;\n");
            asm volatile("cp.async.wait_group 1;\n");
        } else {
            asm volatile("cp.async.wait_group 0;\n");
        }
        __syncthreads();

        #pragma unroll
        for (int ks = 0; ks < 2; ks++) {
            int kb = ks * 16;
            unsigned af[4][4], bfr[4][2];
            #pragma unroll
            for (int i = 0; i < 4; i++) {
                int mr = wm * 64 + i * 16 + g;
                af[i][0] = *(const unsigned*)&As[buf][mr    ][kb + 2 * tg    ];
                af[i][1] = *(const unsigned*)&As[buf][mr + 8][kb + 2 * tg    ];
                af[i][2] = *(const unsigned*)&As[buf][mr    ][kb + 2 * tg + 8];
                af[i][3] = *(const unsigned*)&As[buf][mr + 8][kb + 2 * tg + 8];
            }
            #pragma unroll
            for (int j = 0; j < 4; j++) {
                int nc = wn * 32 + j * 8 + g;
                bfr[j][0] = *(const unsigned*)&Bs[buf][nc][kb + 2 * tg    ];
                bfr[j][1] = *(const unsigned*)&Bs[buf][nc][kb + 2 * tg + 8];
            }
            #pragma unroll
            for (int i = 0; i < 4; i++)
                #pragma unroll
                for (int j = 0; j < 4; j++)
                    MMA_BF16(acc[i][j], af[i][0], af[i][1], af[i][2], af[i][3],
                             bfr[j][0], bfr[j][1]);
        }
        __syncthreads();
    }

    // --- epilogue ---
    #pragma unroll
    for (int i = 0; i < 4; i++) {
        int rbase = m0 + wm * 64 + i * 16 + g;
        #pragma unroll
        for (int j = 0; j < 4; j++) {
            int cbase = n0 + wn * 32 + j * 8 + tg * 2;
            #pragma unroll
            for (int hh = 0; hh < 2; hh++) {
                int rr = rbase + hh * 8;
                #pragma unroll
                for (int cc = 0; cc < 2; cc++) {
                    int nn = cbase + cc;
                    float v = acc[i][j][hh * 2 + cc];
                    if (MODE == EP_HEAD) {
                        // q slab: plain fp32; k/v slabs: tf32 bit pattern
                        float w = (slab == 0) ? v : __uint_as_float(cvt_tf32(v));
                        C[(size_t)((nn >> 6) * T_ + rr) * 64 + (nn & 63)] = w;
                    } else if (MODE == EP_BIASRES) {
                        C[(size_t)rr * N + nn] = v + bias[nn] + res[(size_t)rr * N + nn];
                    } else if (MODE == EP_BIAS) {
                        C[(size_t)rr * N + nn] = v + bias[nn];
                    } else { // EP_SWIGLU
                        float a = aux[(size_t)rr * N + nn];
                        float sig = 1.f / (1.f + __expf(-a));
                        Cb[(size_t)rr * N + nn] = __float2bfloat16((a * sig) * (v + bias[nn]));
                    }
                }
            }
        }
    }
    #undef CPA
    #undef CPB
}

// ---------------- causal flash attention, tf32 MMA ---------------------------
// K/V arrive as tf32 bit patterns (converted in the QKV epilogue) -> zero cvt
// in the S and PV inner loops. K/V tiles cp.async double-buffered.
#define FAP 68

__global__ void __launch_bounds__(256, 2) attn_mma_kernel(
    const float* __restrict__ q, const unsigned* __restrict__ k,
    const unsigned* __restrict__ v, __nv_bfloat16* __restrict__ ctx)
{
    extern __shared__ unsigned smu[];
    unsigned* Ks = smu;                       // [2][64][FAP] tf32 bits
    unsigned* Vs = smu + 2 * 64 * FAP;        // [2][64][FAP] tf32 bits
    unsigned* Ps = smu + 4 * 64 * FAP;        // [128][FAP]   tf32 bits

    int tid = threadIdx.x;
    int warp = tid >> 5, lane = tid & 31;
    int g = lane >> 2, tg = lane & 3;
    int qt = gridDim.x - 1 - blockIdx.x;      // big tiles first
    int h = blockIdx.y;
    int qm0 = qt * 128;
    const float*    qh = q + (size_t)h * (T_ * HD_);
    const unsigned* kh = k + (size_t)h * (T_ * HD_);
    const unsigned* vh = v + (size_t)h * (T_ * HD_);

    int r0 = qm0 + warp * 16 + g;
    int r1 = r0 + 8;
    int wlast = qm0 + warp * 16 + 15;         // warp's last Q row

    unsigned qf[8][4];
    #pragma unroll
    for (int kc = 0; kc < 8; kc++) {
        qf[kc][0] = cvt_tf32(qh[(size_t)r0 * 64 + kc * 8 + tg    ] * 0.125f);
        qf[kc][1] = cvt_tf32(qh[(size_t)r1 * 64 + kc * 8 + tg    ] * 0.125f);
        qf[kc][2] = cvt_tf32(qh[(size_t)r0 * 64 + kc * 8 + tg + 4] * 0.125f);
        qf[kc][3] = cvt_tf32(qh[(size_t)r1 * 64 + kc * 8 + tg + 4] * 0.125f);
    }

    float oacc[8][4] = {};
    float m0 = -1e30f, m1 = -1e30f, l0 = 0.f, l1 = 0.f;
    int nkt = 2 * qt + 2;

    // cp.async both K and V rows for tile kt into buffer b (8 x 16B per thread)
    #define CPKV(b, kt) do {                                                    \
        int km_ = (kt) * 64;                                                    \
        _Pragma("unroll")                                                       \
        for (int e = 0; e < 4; e++) {                                           \
            int idx = tid + e * 256;                                            \
            int r_ = idx >> 4, c_ = (idx & 15) * 4;                             \
            unsigned kd_ = (unsigned)__cvta_generic_to_shared(                  \
                &Ks[(b) * 64 * FAP + r_ * FAP + c_]);                           \
            asm volatile("cp.async.cg.shared.global [%0], [%1], 16;\n"          \
                :: "r"(kd_), "l"(kh + (size_t)(km_ + r_) * 64 + c_));           \
            unsigned vd_ = (unsigned)__cvta_generic_to_shared(                  \
                &Vs[(b) * 64 * FAP + r_ * FAP + c_]);                           \
            asm volatile("cp.async.cg.shared.global [%0], [%1], 16;\n"          \
                :: "r"(vd_), "l"(vh + (size_t)(km_ + r_) * 64 + c_));           \
        }                                                                       \
    } while (0)

    CPKV(0, 0);
    asm volatile("cp.async.commit_group;\n");

    for (int kt = 0; kt < nkt; kt++) {
        int buf = kt & 1;
        if (kt + 1 < nkt) {
            CPKV(buf ^ 1, kt + 1);
            asm volatile("cp.async.commit_group;\n");
            asm volatile("cp.async.wait_group 1;\n");
        } else {
            asm volatile("cp.async.wait_group 0;\n");
        }
        __syncthreads();
        int km0 = kt * 64;

        if (km0 <= wlast) {    // skip fully-masked tile (no-op for m/l/oacc)
            const unsigned* Kb = Ks + buf * 64 * FAP;
            const unsigned* Vb = Vs + buf * 64 * FAP;

            // ---- S = Q K^T ----
            float sacc[8][4] = {};
            #pragma unroll
            for (int kc = 0; kc < 8; kc++) {
                #pragma unroll
                for (int j = 0; j < 8; j++) {
                    unsigned b0 = Kb[(j * 8 + g) * FAP + kc * 8 + tg    ];
                    unsigned b1 = Kb[(j * 8 + g) * FAP + kc * 8 + tg + 4];
                    MMA_TF32(sacc[j], qf[kc][0], qf[kc][1], qf[kc][2], qf[kc][3], b0, b1);
                }
            }

            // ---- causal mask (diagonal tiles only) ----
            if (km0 + 63 > qm0 + warp * 16) {
                #pragma unroll
                for (int j = 0; j < 8; j++) {
                    int c0 = km0 + j * 8 + tg * 2, c1 = c0 + 1;
                    if (c0 > r0) sacc[j][0] = -1e30f;
                    if (c1 > r0) sacc[j][1] = -1e30f;
                    if (c0 > r1) sacc[j][2] = -1e30f;
                    if (c1 > r1) sacc[j][3] = -1e30f;
                }
            }

            // ---- online softmax ----
            float t0 = -1e30f, t1 = -1e30f;
            #pragma unroll
            for (int j = 0; j < 8; j++) {
                t0 = fmaxf(t0, fmaxf(sacc[j][0], sacc[j][1]));
                t1 = fmaxf(t1, fmaxf(sacc[j][2], sacc[j][3]));
            }
            t0 = fmaxf(t0, __shfl_xor_sync(0xffffffffu, t0, 1));
            t0 = fmaxf(t0, __shfl_xor_sync(0xffffffffu, t0, 2));
            t1 = fmaxf(t1, __shfl_xor_sync(0xffffffffu, t1, 1));
            t1 = fmaxf(t1, __shfl_xor_sync(0xffffffffu, t1, 2));
            float nm0 = fmaxf(m0, t0), nm1 = fmaxf(m1, t1);
            float rs0 = __expf(m0 - nm0), rs1 = __expf(m1 - nm1);
            m0 = nm0; m1 = nm1;

            int pr0 = (warp * 16 + g) * FAP, pr1 = pr0 + 8 * FAP;
            float sum0 = 0.f, sum1 = 0.f;
            #pragma unroll
            for (int j = 0; j < 8; j++) {
                float p00 = __expf(sacc[j][0] - m0);
                float p01 = __expf(sacc[j][1] - m0);
                float p10 = __expf(sacc[j][2] - m1);
                float p11 = __expf(sacc[j][3] - m1);
                sum0 += p00 + p01; sum1 += p10 + p11;
                int c = j * 8 + tg * 2;
                Ps[pr0 + c] = cvt_tf32(p00); Ps[pr0 + c + 1] = cvt_tf32(p01);
                Ps[pr1 + c] = cvt_tf32(p10); Ps[pr1 + c + 1] = cvt_tf32(p11);
            }
            l0 = l0 * rs0 + sum0;
            l1 = l1 * rs1 + sum1;
            #pragma unroll
            for (int j = 0; j < 8; j++) {
                oacc[j][0] *= rs0; oacc[j][1] *= rs0;
                oacc[j][2] *= rs1; oacc[j][3] *= rs1;
            }
            __syncwarp();   // Ps visible within warp (rows are warp-private)

            // ---- O += P V ----
            #pragma unroll
            for (int kc = 0; kc < 8; kc++) {
                unsigned a0 = Ps[pr0 + kc * 8 + tg    ];
                unsigned a1 = Ps[pr1 + kc * 8 + tg    ];
                unsigned a2 = Ps[pr0 + kc * 8 + tg + 4];
                unsigned a3 = Ps[pr1 + kc * 8 + tg + 4];
                #pragma unroll
                for (int j = 0; j < 8; j++) {
                    unsigned b0 = Vb[(kc * 8 + tg    ) * FAP + j * 8 + g];
                    unsigned b1 = Vb[(kc * 8 + tg + 4) * FAP + j * 8 + g];
                    MMA_TF32(oacc[j], a0, a1, a2, a3, b0, b1);
                }
            }
            __syncwarp();
        }
        __syncthreads();   // all reads of buf done before it is refilled
    }

    l0 += __shfl_xor_sync(0xffffffffu, l0, 1);
    l0 += __shfl_xor_sync(0xffffffffu, l0, 2);
    l1 += __shfl_xor_sync(0xffffffffu, l1, 1);
    l1 += __shfl_xor_sync(0xffffffffu, l1, 2);
    float inv0 = 1.f / l0, inv1 = 1.f / l1;
    #pragma unroll
    for (int j = 0; j < 8; j++) {
        int col = h * 64 + j * 8 + tg * 2;
        ctx[(size_t)r0 * D_ + col    ] = __float2bfloat16(oacc[j][0] * inv0);
        ctx[(size_t)r0 * D_ + col + 1] = __float2bfloat16(oacc[j][1] * inv0);
        ctx[(size_t)r1 * D_ + col    ] = __float2bfloat16(oacc[j][2] * inv1);
        ctx[(size_t)r1 * D_ + col + 1] = __float2bfloat16(oacc[j][3] * inv1);
    }
    #undef CPKV
}

// ---------------- launch -----------------------------------------------------
extern "C" void kernel_launch(void* const* d_in, const int* in_sizes, int n_in,
                              void* d_out, int out_size) {
    const float* x  = (const float*)d_in[0];
    const float* Wq = (const float*)d_in[1];
    const float* Wk = (const float*)d_in[2];
    const float* Wv = (const float*)d_in[3];
    const float* Wo = (const float*)d_in[4];
    const float* bo = (const float*)d_in[5];
    const float* w1 = (const float*)d_in[6];
    const float* b1 = (const float*)d_in[7];
    const float* w2 = (const float*)d_in[8];
    const float* b2 = (const float*)d_in[9];
    const float* w3 = (const float*)d_in[10];
    const float* b3 = (const float*)d_in[11];
    const float* g1 = (const float*)d_in[12];
    const float* s1 = (const float*)d_in[13];
    const float* g2 = (const float*)d_in[14];
    const float* s2 = (const float*)d_in[15];
    float* out = (float*)d_out;

    __nv_bfloat16 *hb, *ctxb, *ffb, *Wqb, *Wkb, *Wvb, *Wob, *w1b, *w2b, *w3b;
    float *qkvb, *x2b, *y1b;
    cudaGetSymbolAddress((void**)&hb,   g_hb);
    cudaGetSymbolAddress((void**)&qkvb, g_qkv);
    cudaGetSymbolAddress((void**)&ctxb, g_ctxb);
    cudaGetSymbolAddress((void**)&x2b,  g_x2);
    cudaGetSymbolAddress((void**)&y1b,  g_y1);
    cudaGetSymbolAddress((void**)&ffb,  g_ffb);
    cudaGetSymbolAddress((void**)&Wqb,  g_Wqb);
    cudaGetSymbolAddress((void**)&Wkb,  g_Wkb);
    cudaGetSymbolAddress((void**)&Wvb,  g_Wvb);
    cudaGetSymbolAddress((void**)&Wob,  g_Wob);
    cudaGetSymbolAddress((void**)&w1b,  g_w1b);
    cudaGetSymbolAddress((void**)&w2b,  g_w2b);
    cudaGetSymbolAddress((void**)&w3b,  g_w3b);

    const int attn_smem = (4 * 64 * FAP + 128 * FAP) * (int)sizeof(unsigned);
    cudaFuncSetAttribute(attn_mma_kernel, cudaFuncAttributeMaxDynamicSharedMemorySize, attn_smem);

    // weight prepass: all 7 conversions in ONE launch
    wconv_all_kernel<<<9216, dim3(32, 8)>>>(Wq, Wk, Wv, Wo, w1, w2, w3);

    dim3 gD(D_ / BN, T_ / BM);        // (6, 32)
    dim3 gQKV(D_ / BN, T_ / BM, 3);   // fused QKV
    dim3 gF(FF_ / BN, T_ / BM);       // (24, 32)

    // 1. LN1 (bf16 out)
    ln_kernel<<<T_, 256>>>(x, g1, s1, hb);
    // 2. fused QKV projections (q fp32; k,v tf32-bits; head-major)
    bf16_gemm<EP_HEAD><<<gQKV, 256>>>(hb, Wqb, Wkb, Wvb, nullptr, nullptr, nullptr,
                                      qkvb, nullptr, D_, D_);
    // 3. causal attention (tf32 MMA; bf16 ctx out)
    attn_mma_kernel<<<dim3(T_ / 128, H_), 256, attn_smem>>>(
        qkvb, (const unsigned*)(qkvb + (size_t)T_ * D_),
        (const unsigned*)(qkvb + (size_t)2 * T_ * D_), ctxb);
    // 4. out projection + bias + residual (fp32 out)
    bf16_gemm<EP_BIASRES><<<gD, 256>>>(ctxb, Wob, nullptr, nullptr, bo, x, nullptr,
                                       x2b, nullptr, D_, D_);
    // 5. LN2 (bf16 out)
    ln_kernel<<<T_, 256>>>(x2b, g2, s2, hb);
    // 6. SwiGLU: y1 = h@w1+b1 (fp32) ; ff = silu(y1) * (h@w2+b2) (bf16)
    bf16_gemm<EP_BIAS>  <<<gF, 256>>>(hb, w1b, nullptr, nullptr, b1, nullptr, nullptr,
                                      y1b, nullptr, FF_, D_);
    bf16_gemm<EP_SWIGLU><<<gF, 256>>>(hb, w2b, nullptr, nullptr, b2, nullptr, y1b,
                                      nullptr, ffb, FF_, D_);
    // 7. down projection + bias + residual -> output (fp32)
    bf16_gemm<EP_BIASRES><<<gD, 256>>>(ffb, w3b, nullptr, nullptr, b3, x2b, nullptr,
                                       out, nullptr, D_, FF_);
}

// round 14
// speedup vs baseline: 1.7896x; 1.1311x over previous
#include <cuda_runtime.h>
#include <cuda_bf16.h>
#include <math.h>

#define T_  4096
#define D_  768
#define H_  12
#define HD_ 64
#define FF_ 3072

// ---------------- scratch (device globals; no allocation allowed) ------------
__device__ __nv_bfloat16 g_hb  [T_ * D_];        // LN output (bf16, GEMM A)
// q slab: [h][t][64] fp32. k slab: [h][t][64] tf32-bits, cols pair-permuted.
// v slab: [h][64][T] tf32-bits (transposed), t pair-permuted within 8-groups.
__device__ float         g_qkv [3 * T_ * D_];
__device__ __nv_bfloat16 g_ctxb[T_ * D_];        // attention out (bf16, GEMM A)
__device__ float         g_x2  [T_ * D_];        // residual after MHA
__device__ float         g_y1  [T_ * FF_];       // h@w1+b1 (fp32)
__device__ __nv_bfloat16 g_ffb [T_ * FF_];       // SwiGLU hidden (bf16, GEMM A)
// weights: bf16, transposed to [n][k]
__device__ __nv_bfloat16 g_Wqb[D_ * D_];
__device__ __nv_bfloat16 g_Wkb[D_ * D_];
__device__ __nv_bfloat16 g_Wvb[D_ * D_];
__device__ __nv_bfloat16 g_Wob[D_ * D_];
__device__ __nv_bfloat16 g_w1b[D_ * FF_];
__device__ __nv_bfloat16 g_w2b[D_ * FF_];
__device__ __nv_bfloat16 g_w3b[FF_ * D_];

// pair-permutation within an 8-group: t -> (t&3)*2 + (t>>2)
// (puts original (tg, tg+4) at adjacent positions (2tg, 2tg+1))
__device__ __forceinline__ int pperm(int t) { return ((t & 3) << 1) | (t >> 2); }

// ---------------- fused weight convert+transpose: fp32 [K][N] -> bf16 [N][K] --
__global__ void wconv_all_kernel(const float* __restrict__ Wq, const float* __restrict__ Wk,
                                 const float* __restrict__ Wv, const float* __restrict__ Wo,
                                 const float* __restrict__ w1, const float* __restrict__ w2,
                                 const float* __restrict__ w3) {
    __shared__ float tile[32][33];
    int fb = blockIdx.x;
    const float* W; __nv_bfloat16* out; int K, N, t;
    if (fb < 2304) {
        int wi = fb / 576; t = fb % 576; K = D_; N = D_;
        W   = (wi == 0) ? Wq : (wi == 1) ? Wk : (wi == 2) ? Wv : Wo;
        out = (wi == 0) ? g_Wqb : (wi == 1) ? g_Wkb : (wi == 2) ? g_Wvb : g_Wob;
    } else if (fb < 6912) {
        int wi = (fb - 2304) / 2304; t = (fb - 2304) % 2304; K = D_; N = FF_;
        W   = (wi == 0) ? w1 : w2;
        out = (wi == 0) ? g_w1b : g_w2b;
    } else {
        t = fb - 6912; K = FF_; N = D_;
        W = w3; out = g_w3b;
    }
    int ntiles = N / 32;
    int n0 = (t % ntiles) * 32, k0 = (t / ntiles) * 32;
    int tx = threadIdx.x, ty = threadIdx.y;   // 32 x 8
    #pragma unroll
    for (int e = 0; e < 4; e++)
        tile[ty + e * 8][tx] = W[(size_t)(k0 + ty + e * 8) * N + n0 + tx];
    __syncthreads();
    #pragma unroll
    for (int e = 0; e < 4; e++)
        out[(size_t)(n0 + ty + e * 8) * K + k0 + tx] = __float2bfloat16(tile[tx][ty + e * 8]);
}

// ---------------- LayerNorm (bf16 output) ------------------------------------
__global__ void ln_kernel(const float* __restrict__ x, const float* __restrict__ g,
                          const float* __restrict__ s, __nv_bfloat16* __restrict__ out) {
    int row = blockIdx.x;
    const float* xr = x + (size_t)row * D_;
    float sum = 0.f, sq = 0.f;
    for (int i = threadIdx.x; i < D_; i += 256) {
        float v = xr[i]; sum += v; sq += v * v;
    }
    __shared__ float ssum[8], ssq[8];
    #pragma unroll
    for (int o = 16; o > 0; o >>= 1) {
        sum += __shfl_down_sync(0xffffffffu, sum, o);
        sq  += __shfl_down_sync(0xffffffffu, sq,  o);
    }
    int w = threadIdx.x >> 5, l = threadIdx.x & 31;
    if (l == 0) { ssum[w] = sum; ssq[w] = sq; }
    __syncthreads();
    if (threadIdx.x == 0) {
        float a = 0.f, b = 0.f;
        #pragma unroll
        for (int i = 0; i < 8; i++) { a += ssum[i]; b += ssq[i]; }
        ssum[0] = a; ssq[0] = b;
    }
    __syncthreads();
    float mean = ssum[0] * (1.f / D_);
    float var  = ssq[0]  * (1.f / D_) - mean * mean;
    float rstd = rsqrtf(var + 1e-5f);
    for (int i = threadIdx.x; i < D_; i += 256)
        out[(size_t)row * D_ + i] = __float2bfloat16(g[i] * (xr[i] - mean) * rstd + s[i]);
}

// ---------------- helpers ------------------------------------------------------
__device__ __forceinline__ unsigned cvt_tf32(float x) {
    unsigned r;
    asm("cvt.rna.tf32.f32 %0, %1;" : "=r"(r) : "f"(x));
    return r;
}

#define MMA_TF32(acc, a0, a1, a2, a3, b0, b1)                                   \
    asm volatile(                                                               \
        "mma.sync.aligned.m16n8k8.row.col.f32.tf32.tf32.f32 "                   \
        "{%0,%1,%2,%3}, {%4,%5,%6,%7}, {%8,%9}, {%0,%1,%2,%3};"                 \
        : "+f"((acc)[0]), "+f"((acc)[1]), "+f"((acc)[2]), "+f"((acc)[3])        \
        : "r"(a0), "r"(a1), "r"(a2), "r"(a3), "r"(b0), "r"(b1))

#define MMA_BF16(acc, a0, a1, a2, a3, b0, b1)                                   \
    asm volatile(                                                               \
        "mma.sync.aligned.m16n8k16.row.col.f32.bf16.bf16.f32 "                  \
        "{%0,%1,%2,%3}, {%4,%5,%6,%7}, {%8,%9}, {%0,%1,%2,%3};"                 \
        : "+f"((acc)[0]), "+f"((acc)[1]), "+f"((acc)[2]), "+f"((acc)[3])        \
        : "r"(a0), "r"(a1), "r"(a2), "r"(a3), "r"(b0), "r"(b1))

// ---------------- bf16 tensor-core GEMM (scalar-LDS inner loop; R11) ----------
#define BM 128
#define BN 128
#define HKB 32      // bf16 k per tile
#define HP  40      // smem pitch in bf16

enum { EP_HEAD = 0, EP_BIASRES = 1, EP_BIAS = 2, EP_SWIGLU = 3 };

template <int MODE>
__global__ void __launch_bounds__(256, 2) bf16_gemm(
    const __nv_bfloat16* __restrict__ A,  const __nv_bfloat16* __restrict__ B,
    const __nv_bfloat16* __restrict__ B1, const __nv_bfloat16* __restrict__ B2,
    const float* __restrict__ bias, const float* __restrict__ res,
    const float* __restrict__ aux,  float* __restrict__ C,
    __nv_bfloat16* __restrict__ Cb, int N, int K)
{
    int slab = 0;
    if (MODE == EP_HEAD) {      // grid.z selects q/k/v weight + output slab
        slab = blockIdx.z;
        if (slab == 1)      { B = B1; C += (size_t)T_ * D_; }
        else if (slab == 2) { B = B2; C += (size_t)2 * T_ * D_; }
    }
    __shared__ __nv_bfloat16 As[2][BM][HP];
    __shared__ __nv_bfloat16 Bs[2][BN][HP];
    int tid = threadIdx.x;
    int warp = tid >> 5, lane = tid & 31;
    int g = lane >> 2, tg = lane & 3;
    int wm = warp >> 2, wn = warp & 3;
    int m0 = blockIdx.y * BM, n0 = blockIdx.x * BN;

    float acc[4][4][4] = {};
    int nk = K / HKB;

    #define CPA(buf, kt) do {                                                   \
        int k0_ = (kt) * HKB;                                                   \
        _Pragma("unroll")                                                       \
        for (int e = 0; e < 2; e++) {                                           \
            int idx = tid + e * 256;                                            \
            int r_ = idx >> 2, c_ = (idx & 3) * 8;                              \
            const __nv_bfloat16* src_ = A + (size_t)(m0 + r_) * K + k0_ + c_;   \
            unsigned dst_ = (unsigned)__cvta_generic_to_shared(&As[buf][r_][c_]); \
            asm volatile("cp.async.cg.shared.global [%0], [%1], 16;\n"          \
                         :: "r"(dst_), "l"(src_));                              \
        }                                                                       \
    } while (0)
    #define CPB(buf, kt) do {                                                   \
        int k0_ = (kt) * HKB;                                                   \
        _Pragma("unroll")                                                       \
        for (int e = 0; e < 2; e++) {                                           \
            int idx = tid + e * 256;                                            \
            int r_ = idx >> 2, c_ = (idx & 3) * 8;                              \
            const __nv_bfloat16* src_ = B + (size_t)(n0 + r_) * K + k0_ + c_;   \
            unsigned dst_ = (unsigned)__cvta_generic_to_shared(&Bs[buf][r_][c_]); \
            asm volatile("cp.async.cg.shared.global [%0], [%1], 16;\n"          \
                         :: "r"(dst_), "l"(src_));                              \
        }                                                                       \
    } while (0)

    CPA(0, 0); CPB(0, 0);
    asm volatile("cp.async.commit_group;\n");

    for (int t = 0; t < nk; t++) {
        int buf = t & 1;
        if (t + 1 < nk) {
            CPA(buf ^ 1, t + 1); CPB(buf ^ 1, t + 1);
            asm volatile("cp.async.commit_group;\n");
            asm volatile("cp.async.wait_group 1;\n");
        } else {
            asm volatile("cp.async.wait_group 0;\n");
        }
        __syncthreads();

        #pragma unroll
        for (int ks = 0; ks < 2; ks++) {
            int kb = ks * 16;
            unsigned af[4][4], bfr[4][2];
            #pragma unroll
            for (int i = 0; i < 4; i++) {
                int mr = wm * 64 + i * 16 + g;
                af[i][0] = *(const unsigned*)&As[buf][mr    ][kb + 2 * tg    ];
                af[i][1] = *(const unsigned*)&As[buf][mr + 8][kb + 2 * tg    ];
                af[i][2] = *(const unsigned*)&As[buf][mr    ][kb + 2 * tg + 8];
                af[i][3] = *(const unsigned*)&As[buf][mr + 8][kb + 2 * tg + 8];
            }
            #pragma unroll
            for (int j = 0; j < 4; j++) {
                int nc = wn * 32 + j * 8 + g;
                bfr[j][0] = *(const unsigned*)&Bs[buf][nc][kb + 2 * tg    ];
                bfr[j][1] = *(const unsigned*)&Bs[buf][nc][kb + 2 * tg + 8];
            }
            #pragma unroll
            for (int i = 0; i < 4; i++)
                #pragma unroll
                for (int j = 0; j < 4; j++)
                    MMA_BF16(acc[i][j], af[i][0], af[i][1], af[i][2], af[i][3],
                             bfr[j][0], bfr[j][1]);
        }
        __syncthreads();
    }

    // --- epilogue ---
    #pragma unroll
    for (int i = 0; i < 4; i++) {
        int rbase = m0 + wm * 64 + i * 16 + g;
        #pragma unroll
        for (int j = 0; j < 4; j++) {
            int cbase = n0 + wn * 32 + j * 8 + tg * 2;
            #pragma unroll
            for (int hh = 0; hh < 2; hh++) {
                int rr = rbase + hh * 8;
                #pragma unroll
                for (int cc = 0; cc < 2; cc++) {
                    int nn = cbase + cc;
                    float v = acc[i][j][hh * 2 + cc];
                    if (MODE == EP_HEAD) {
                        int hd = nn >> 6, d = nn & 63;
                        if (slab == 0) {            // q: [h][t][64] fp32
                            C[(size_t)(hd * T_ + rr) * 64 + d] = v;
                        } else if (slab == 1) {     // k: [h][t][64] tf32, col-perm
                            int dp = (d & ~7) + pperm(d & 7);
                            C[(size_t)(hd * T_ + rr) * 64 + dp] =
                                __uint_as_float(cvt_tf32(v));
                        } else {                    // v: [h][64][T] tf32, t-perm
                            int rp = (rr & ~7) + pperm(rr & 7);
                            C[(size_t)(hd * 64 + d) * T_ + rp] =
                                __uint_as_float(cvt_tf32(v));
                        }
                    } else if (MODE == EP_BIASRES) {
                        C[(size_t)rr * N + nn] = v + bias[nn] + res[(size_t)rr * N + nn];
                    } else if (MODE == EP_BIAS) {
                        C[(size_t)rr * N + nn] = v + bias[nn];
                    } else { // EP_SWIGLU
                        float a = aux[(size_t)rr * N + nn];
                        float sig = 1.f / (1.f + __expf(-a));
                        Cb[(size_t)rr * N + nn] = __float2bfloat16((a * sig) * (v + bias[nn]));
                    }
                }
            }
        }
    }
    #undef CPA
    #undef CPB
}

// ---------------- causal flash attention, tf32 MMA ---------------------------
// K: [t][64] tf32-bits with pair-permuted cols; V: [64][T] tf32-bits with
// pair-permuted t. All fragment loads are LDS.64 (uint2). Pitch 72 words
// -> (8g+2tg) mod 32 distinct per half-warp: conflict-free 64-bit accesses.
#define KVP 72

__global__ void __launch_bounds__(256, 2) attn_mma_kernel(
    const float* __restrict__ q, const unsigned* __restrict__ k,
    const unsigned* __restrict__ v, __nv_bfloat16* __restrict__ ctx)
{
    extern __shared__ unsigned smu[];
    unsigned* Ks = smu;                        // [2][64][KVP]
    unsigned* Vs = smu + 2 * 64 * KVP;         // [2][64][KVP]  (rows = d!)
    unsigned* Ps = smu + 4 * 64 * KVP;         // [128][KVP]

    int tid = threadIdx.x;
    int warp = tid >> 5, lane = tid & 31;
    int g = lane >> 2, tg = lane & 3;
    int qt = gridDim.x - 1 - blockIdx.x;       // big tiles first
    int h = blockIdx.y;
    int qm0 = qt * 128;
    const float*    qh = q + (size_t)h * (T_ * HD_);
    const unsigned* kh = k + (size_t)h * (T_ * HD_);
    const unsigned* vh = v + (size_t)h * (T_ * HD_);   // [64][T] layout

    int r0 = qm0 + warp * 16 + g;
    int r1 = r0 + 8;
    int wlast = qm0 + warp * 16 + 15;

    // P store positions for original cols (2tg, 2tg+1) under pair-permutation
    int pa = pperm(2 * tg), pb = pperm(2 * tg + 1);

    unsigned qf[8][4];
    #pragma unroll
    for (int kc = 0; kc < 8; kc++) {
        qf[kc][0] = cvt_tf32(qh[(size_t)r0 * 64 + kc * 8 + tg    ] * 0.125f);
        qf[kc][1] = cvt_tf32(qh[(size_t)r1 * 64 + kc * 8 + tg    ] * 0.125f);
        qf[kc][2] = cvt_tf32(qh[(size_t)r0 * 64 + kc * 8 + tg + 4] * 0.125f);
        qf[kc][3] = cvt_tf32(qh[(size_t)r1 * 64 + kc * 8 + tg + 4] * 0.125f);
    }

    float oacc[8][4] = {};
    float m0 = -1e30f, m1 = -1e30f, l0 = 0.f, l1 = 0.f;
    int nkt = 2 * qt + 2;

    // K rows: [t][64] contiguous; V rows: [d][T] -> 64 contiguous t at km0
    #define CPKV(b, kt) do {                                                    \
        int km_ = (kt) * 64;                                                    \
        _Pragma("unroll")                                                       \
        for (int e = 0; e < 4; e++) {                                           \
            int idx = tid + e * 256;                                            \
            int r_ = idx >> 4, c_ = (idx & 15) * 4;                             \
            unsigned kd_ = (unsigned)__cvta_generic_to_shared(                  \
                &Ks[(b) * 64 * KVP + r_ * KVP + c_]);                           \
            asm volatile("cp.async.cg.shared.global [%0], [%1], 16;\n"          \
                :: "r"(kd_), "l"(kh + (size_t)(km_ + r_) * 64 + c_));           \
            unsigned vd_ = (unsigned)__cvta_generic_to_shared(                  \
                &Vs[(b) * 64 * KVP + r_ * KVP + c_]);                           \
            asm volatile("cp.async.cg.shared.global [%0], [%1], 16;\n"          \
                :: "r"(vd_), "l"(vh + (size_t)r_ * T_ + km_ + c_));             \
        }                                                                       \
    } while (0)

    CPKV(0, 0);
    asm volatile("cp.async.commit_group;\n");

    for (int kt = 0; kt < nkt; kt++) {
        int buf = kt & 1;
        if (kt + 1 < nkt) {
            CPKV(buf ^ 1, kt + 1);
            asm volatile("cp.async.commit_group;\n");
            asm volatile("cp.async.wait_group 1;\n");
        } else {
            asm volatile("cp.async.wait_group 0;\n");
        }
        __syncthreads();
        int km0 = kt * 64;

        if (km0 <= wlast) {    // skip fully-masked tiles
            const unsigned* Kb = Ks + buf * 64 * KVP;
            const unsigned* Vb = Vs + buf * 64 * KVP;

            // ---- S = Q K^T ----
            float sacc[8][4] = {};
            #pragma unroll
            for (int kc = 0; kc < 8; kc++) {
                #pragma unroll
                for (int j = 0; j < 8; j++) {
                    uint2 bb = *(const uint2*)&Kb[(j * 8 + g) * KVP + kc * 8 + 2 * tg];
                    MMA_TF32(sacc[j], qf[kc][0], qf[kc][1], qf[kc][2], qf[kc][3],
                             bb.x, bb.y);
                }
            }

            // ---- causal mask (diagonal tiles only) ----
            if (km0 + 63 > qm0 + warp * 16) {
                #pragma unroll
                for (int j = 0; j < 8; j++) {
                    int c0 = km0 + j * 8 + tg * 2, c1 = c0 + 1;
                    if (c0 > r0) sacc[j][0] = -1e30f;
                    if (c1 > r0) sacc[j][1] = -1e30f;
                    if (c0 > r1) sacc[j][2] = -1e30f;
                    if (c1 > r1) sacc[j][3] = -1e30f;
                }
            }

            // ---- online softmax ----
            float t0 = -1e30f, t1 = -1e30f;
            #pragma unroll
            for (int j = 0; j < 8; j++) {
                t0 = fmaxf(t0, fmaxf(sacc[j][0], sacc[j][1]));
                t1 = fmaxf(t1, fmaxf(sacc[j][2], sacc[j][3]));
            }
            t0 = fmaxf(t0, __shfl_xor_sync(0xffffffffu, t0, 1));
            t0 = fmaxf(t0, __shfl_xor_sync(0xffffffffu, t0, 2));
            t1 = fmaxf(t1, __shfl_xor_sync(0xffffffffu, t1, 1));
            t1 = fmaxf(t1, __shfl_xor_sync(0xffffffffu, t1, 2));
            float nm0 = fmaxf(m0, t0), nm1 = fmaxf(m1, t1);
            float rs0 = __expf(m0 - nm0), rs1 = __expf(m1 - nm1);
            m0 = nm0; m1 = nm1;

            int pr0 = (warp * 16 + g) * KVP, pr1 = pr0 + 8 * KVP;
            float sum0 = 0.f, sum1 = 0.f;
            #pragma unroll
            for (int j = 0; j < 8; j++) {
                float p00 = __expf(sacc[j][0] - m0);
                float p01 = __expf(sacc[j][1] - m0);
                float p10 = __expf(sacc[j][2] - m1);
                float p11 = __expf(sacc[j][3] - m1);
                sum0 += p00 + p01; sum1 += p10 + p11;
                Ps[pr0 + j * 8 + pa] = cvt_tf32(p00);
                Ps[pr0 + j * 8 + pb] = cvt_tf32(p01);
                Ps[pr1 + j * 8 + pa] = cvt_tf32(p10);
                Ps[pr1 + j * 8 + pb] = cvt_tf32(p11);
            }
            l0 = l0 * rs0 + sum0;
            l1 = l1 * rs1 + sum1;
            #pragma unroll
            for (int j = 0; j < 8; j++) {
                oacc[j][0] *= rs0; oacc[j][1] *= rs0;
                oacc[j][2] *= rs1; oacc[j][3] *= rs1;
            }
            __syncwarp();   // Ps rows are warp-private

            // ---- O += P V ----
            #pragma unroll
            for (int kc = 0; kc < 8; kc++) {
                uint2 aA = *(const uint2*)&Ps[pr0 + kc * 8 + 2 * tg]; // a0,a2
                uint2 aB = *(const uint2*)&Ps[pr1 + kc * 8 + 2 * tg]; // a1,a3
                #pragma unroll
                for (int j = 0; j < 8; j++) {
                    uint2 bb = *(const uint2*)&Vb[(j * 8 + g) * KVP + kc * 8 + 2 * tg];
                    MMA_TF32(oacc[j], aA.x, aB.x, aA.y, aB.y, bb.x, bb.y);
                }
            }
            __syncwarp();
        }
        __syncthreads();   // all reads of buf done before refill
    }

    l0 += __shfl_xor_sync(0xffffffffu, l0, 1);
    l0 += __shfl_xor_sync(0xffffffffu, l0, 2);
    l1 += __shfl_xor_sync(0xffffffffu, l1, 1);
    l1 += __shfl_xor_sync(0xffffffffu, l1, 2);
    float inv0 = 1.f / l0, inv1 = 1.f / l1;
    #pragma unroll
    for (int j = 0; j < 8; j++) {
        int col = h * 64 + j * 8 + tg * 2;
        ctx[(size_t)r0 * D_ + col    ] = __float2bfloat16(oacc[j][0] * inv0);
        ctx[(size_t)r0 * D_ + col + 1] = __float2bfloat16(oacc[j][1] * inv0);
        ctx[(size_t)r1 * D_ + col    ] = __float2bfloat16(oacc[j][2] * inv1);
        ctx[(size_t)r1 * D_ + col + 1] = __float2bfloat16(oacc[j][3] * inv1);
    }
    #undef CPKV
}

// ---------------- launch -----------------------------------------------------
extern "C" void kernel_launch(void* const* d_in, const int* in_sizes, int n_in,
                              void* d_out, int out_size) {
    const float* x  = (const float*)d_in[0];
    const float* Wq = (const float*)d_in[1];
    const float* Wk = (const float*)d_in[2];
    const float* Wv = (const float*)d_in[3];
    const float* Wo = (const float*)d_in[4];
    const float* bo = (const float*)d_in[5];
    const float* w1 = (const float*)d_in[6];
    const float* b1 = (const float*)d_in[7];
    const float* w2 = (const float*)d_in[8];
    const float* b2 = (const float*)d_in[9];
    const float* w3 = (const float*)d_in[10];
    const float* b3 = (const float*)d_in[11];
    const float* g1 = (const float*)d_in[12];
    const float* s1 = (const float*)d_in[13];
    const float* g2 = (const float*)d_in[14];
    const float* s2 = (const float*)d_in[15];
    float* out = (float*)d_out;

    __nv_bfloat16 *hb, *ctxb, *ffb, *Wqb, *Wkb, *Wvb, *Wob, *w1b, *w2b, *w3b;
    float *qkvb, *x2b, *y1b;
    cudaGetSymbolAddress((void**)&hb,   g_hb);
    cudaGetSymbolAddress((void**)&qkvb, g_qkv);
    cudaGetSymbolAddress((void**)&ctxb, g_ctxb);
    cudaGetSymbolAddress((void**)&x2b,  g_x2);
    cudaGetSymbolAddress((void**)&y1b,  g_y1);
    cudaGetSymbolAddress((void**)&ffb,  g_ffb);
    cudaGetSymbolAddress((void**)&Wqb,  g_Wqb);
    cudaGetSymbolAddress((void**)&Wkb,  g_Wkb);
    cudaGetSymbolAddress((void**)&Wvb,  g_Wvb);
    cudaGetSymbolAddress((void**)&Wob,  g_Wob);
    cudaGetSymbolAddress((void**)&w1b,  g_w1b);
    cudaGetSymbolAddress((void**)&w2b,  g_w2b);
    cudaGetSymbolAddress((void**)&w3b,  g_w3b);

    const int attn_smem = (4 * 64 * KVP + 128 * KVP) * (int)sizeof(unsigned);
    cudaFuncSetAttribute(attn_mma_kernel, cudaFuncAttributeMaxDynamicSharedMemorySize, attn_smem);

    // weight prepass: all 7 conversions in ONE launch
    wconv_all_kernel<<<9216, dim3(32, 8)>>>(Wq, Wk, Wv, Wo, w1, w2, w3);

    dim3 gD(D_ / BN, T_ / BM);        // (6, 32)
    dim3 gQKV(D_ / BN, T_ / BM, 3);   // fused QKV
    dim3 gF(FF_ / BN, T_ / BM);       // (24, 32)

    // 1. LN1 (bf16 out)
    ln_kernel<<<T_, 256>>>(x, g1, s1, hb);
    // 2. fused QKV projections (q fp32; k col-perm tf32; v transposed tf32)
    bf16_gemm<EP_HEAD><<<gQKV, 256>>>(hb, Wqb, Wkb, Wvb, nullptr, nullptr, nullptr,
                                      qkvb, nullptr, D_, D_);
    // 3. causal attention (tf32 MMA; bf16 ctx out)
    attn_mma_kernel<<<dim3(T_ / 128, H_), 256, attn_smem>>>(
        qkvb, (const unsigned*)(qkvb + (size_t)T_ * D_),
        (const unsigned*)(qkvb + (size_t)2 * T_ * D_), ctxb);
    // 4. out projection + bias + residual (fp32 out)
    bf16_gemm<EP_BIASRES><<<gD, 256>>>(ctxb, Wob, nullptr, nullptr, bo, x, nullptr,
                                       x2b, nullptr, D_, D_);
    // 5. LN2 (bf16 out)
    ln_kernel<<<T_, 256>>>(x2b, g2, s2, hb);
    // 6. SwiGLU: y1 = h@w1+b1 (fp32) ; ff = silu(y1) * (h@w2+b2) (bf16)
    bf16_gemm<EP_BIAS>  <<<gF, 256>>>(hb, w1b, nullptr, nullptr, b1, nullptr, nullptr,
                                      y1b, nullptr, FF_, D_);
    bf16_gemm<EP_SWIGLU><<<gF, 256>>>(hb, w2b, nullptr, nullptr, b2, nullptr, y1b,
                                      nullptr, ffb, FF_, D_);
    // 7. down projection + bias + residual -> output (fp32)
    bf16_gemm<EP_BIASRES><<<gD, 256>>>(ffb, w3b, nullptr, nullptr, b3, x2b, nullptr,
                                       out, nullptr, D_, FF_);
}

// round 17
// speedup vs baseline: 1.8988x; 1.0611x over previous
#include <cuda_runtime.h>
#include <cuda_bf16.h>
#include <cstdint>
#include <math.h>

#define T_  4096
#define D_  768
#define H_  12
#define HD_ 64
#define FF_ 3072

// tiled-weight geometry: blocks of [128 n-rows][40 bf16 pitch] = 5120 elems
#define WBLK 5120

// ---------------- scratch (device globals; no allocation allowed) ------------
__device__ __nv_bfloat16 g_hb  [T_ * D_];        // LN output (bf16, GEMM A)
// q slab: [h][t][64] fp32. k slab: [h][t][64] tf32-bits, cols pair-permuted.
// v slab: [h][64][T] tf32-bits (transposed), t pair-permuted within 8-groups.
__device__ float         g_qkv [3 * T_ * D_];
__device__ __nv_bfloat16 g_ctxb[T_ * D_];        // attention out (bf16, GEMM A)
__device__ float         g_x2  [T_ * D_];        // residual after MHA
__device__ float         g_y1  [T_ * FF_];       // h@w1+b1 (fp32)
__device__ __nv_bfloat16 g_ffb [T_ * FF_];       // SwiGLU hidden (bf16, GEMM A)
// weights: bf16, TILED [nblk][kchunk][128][40] (smem-image blocks, 10240B each)
__device__ __nv_bfloat16 g_Wqb[(D_/128)*(D_/32)*WBLK];
__device__ __nv_bfloat16 g_Wkb[(D_/128)*(D_/32)*WBLK];
__device__ __nv_bfloat16 g_Wvb[(D_/128)*(D_/32)*WBLK];
__device__ __nv_bfloat16 g_Wob[(D_/128)*(D_/32)*WBLK];
__device__ __nv_bfloat16 g_w1b[(FF_/128)*(D_/32)*WBLK];
__device__ __nv_bfloat16 g_w2b[(FF_/128)*(D_/32)*WBLK];
__device__ __nv_bfloat16 g_w3b[(D_/128)*(FF_/32)*WBLK];

// pair-permutation within an 8-group: t -> (t&3)*2 + (t>>2)
__device__ __forceinline__ int pperm(int t) { return ((t & 3) << 1) | (t >> 2); }

// ---------------- fused weight convert+transpose+tile ------------------------
// fp32 [K][N] -> bf16 tiled [n>>7][k>>5][n&127][40] (k&31 in cols 0..31)
__global__ void wconv_all_kernel(const float* __restrict__ Wq, const float* __restrict__ Wk,
                                 const float* __restrict__ Wv, const float* __restrict__ Wo,
                                 const float* __restrict__ w1, const float* __restrict__ w2,
                                 const float* __restrict__ w3) {
    __shared__ float tile[32][33];
    int fb = blockIdx.x;
    const float* W; __nv_bfloat16* out; int K, N, t;
    if (fb < 2304) {
        int wi = fb / 576; t = fb % 576; K = D_; N = D_;
        W   = (wi == 0) ? Wq : (wi == 1) ? Wk : (wi == 2) ? Wv : Wo;
        out = (wi == 0) ? g_Wqb : (wi == 1) ? g_Wkb : (wi == 2) ? g_Wvb : g_Wob;
    } else if (fb < 6912) {
        int wi = (fb - 2304) / 2304; t = (fb - 2304) % 2304; K = D_; N = FF_;
        W   = (wi == 0) ? w1 : w2;
        out = (wi == 0) ? g_w1b : g_w2b;
    } else {
        t = fb - 6912; K = FF_; N = D_;
        W = w3; out = g_w3b;
    }
    int ntiles = N / 32;
    int n0 = (t % ntiles) * 32, k0 = (t / ntiles) * 32;
    int tx = threadIdx.x, ty = threadIdx.y;   // 32 x 8
    #pragma unroll
    for (int e = 0; e < 4; e++)
        tile[ty + e * 8][tx] = W[(size_t)(k0 + ty + e * 8) * N + n0 + tx];
    __syncthreads();
    // write: n = n0+ty+e*8, k = k0+tx  (k consecutive across tx -> coalesced 64B)
    #pragma unroll
    for (int e = 0; e < 4; e++) {
        int n = n0 + ty + e * 8, k = k0 + tx;
        size_t off = ((size_t)(n >> 7) * (K >> 5) + (k >> 5)) * WBLK
                     + (size_t)(n & 127) * 40 + (k & 31);
        out[off] = __float2bfloat16(tile[tx][ty + e * 8]);
    }
}

// ---------------- LayerNorm (bf16 output) ------------------------------------
__global__ void ln_kernel(const float* __restrict__ x, const float* __restrict__ g,
                          const float* __restrict__ s, __nv_bfloat16* __restrict__ out) {
    int row = blockIdx.x;
    const float* xr = x + (size_t)row * D_;
    float sum = 0.f, sq = 0.f;
    for (int i = threadIdx.x; i < D_; i += 256) {
        float v = xr[i]; sum += v; sq += v * v;
    }
    __shared__ float ssum[8], ssq[8];
    #pragma unroll
    for (int o = 16; o > 0; o >>= 1) {
        sum += __shfl_down_sync(0xffffffffu, sum, o);
        sq  += __shfl_down_sync(0xffffffffu, sq,  o);
    }
    int w = threadIdx.x >> 5, l = threadIdx.x & 31;
    if (l == 0) { ssum[w] = sum; ssq[w] = sq; }
    __syncthreads();
    if (threadIdx.x == 0) {
        float a = 0.f, b = 0.f;
        #pragma unroll
        for (int i = 0; i < 8; i++) { a += ssum[i]; b += ssq[i]; }
        ssum[0] = a; ssq[0] = b;
    }
    __syncthreads();
    float mean = ssum[0] * (1.f / D_);
    float var  = ssq[0]  * (1.f / D_) - mean * mean;
    float rstd = rsqrtf(var + 1e-5f);
    for (int i = threadIdx.x; i < D_; i += 256)
        out[(size_t)row * D_ + i] = __float2bfloat16(g[i] * (xr[i] - mean) * rstd + s[i]);
}

// ---------------- helpers ------------------------------------------------------
__device__ __forceinline__ unsigned cvt_tf32(float x) {
    unsigned r;
    asm("cvt.rna.tf32.f32 %0, %1;" : "=r"(r) : "f"(x));
    return r;
}

__device__ __forceinline__ void mbar_wait(unsigned mb, int phase) {
    asm volatile(
        "{\n\t.reg .pred P;\n"
        "LAB%=:\n\t"
        "mbarrier.try_wait.parity.shared::cta.b64 P, [%0], %1;\n\t"
        "@!P bra LAB%=;\n\t}"
        :: "r"(mb), "r"((unsigned)phase) : "memory");
}

#define MMA_TF32(acc, a0, a1, a2, a3, b0, b1)                                   \
    asm volatile(                                                               \
        "mma.sync.aligned.m16n8k8.row.col.f32.tf32.tf32.f32 "                   \
        "{%0,%1,%2,%3}, {%4,%5,%6,%7}, {%8,%9}, {%0,%1,%2,%3};"                 \
        : "+f"((acc)[0]), "+f"((acc)[1]), "+f"((acc)[2]), "+f"((acc)[3])        \
        : "r"(a0), "r"(a1), "r"(a2), "r"(a3), "r"(b0), "r"(b1))

#define MMA_BF16(acc, a0, a1, a2, a3, b0, b1)                                   \
    asm volatile(                                                               \
        "mma.sync.aligned.m16n8k16.row.col.f32.bf16.bf16.f32 "                  \
        "{%0,%1,%2,%3}, {%4,%5,%6,%7}, {%8,%9}, {%0,%1,%2,%3};"                 \
        : "+f"((acc)[0]), "+f"((acc)[1]), "+f"((acc)[2]), "+f"((acc)[3])        \
        : "r"(a0), "r"(a1), "r"(a2), "r"(a3), "r"(b0), "r"(b1))

// ---------------- bf16 tensor-core GEMM --------------------------------------
// A via cp.async; B via single cp.async.bulk per chunk from pre-tiled weights.
#define BM 128
#define BN 128
#define HKB 32      // bf16 k per tile
#define HP  40      // smem pitch in bf16

enum { EP_HEAD = 0, EP_BIASRES = 1, EP_BIAS = 2, EP_SWIGLU = 3 };

template <int MODE>
__global__ void __launch_bounds__(256, 2) bf16_gemm(
    const __nv_bfloat16* __restrict__ A,  const __nv_bfloat16* __restrict__ B,
    const __nv_bfloat16* __restrict__ B1, const __nv_bfloat16* __restrict__ B2,
    const float* __restrict__ bias, const float* __restrict__ res,
    const float* __restrict__ aux,  float* __restrict__ C,
    __nv_bfloat16* __restrict__ Cb, int N, int K)
{
    int slab = 0;
    if (MODE == EP_HEAD) {      // grid.z selects q/k/v weight + output slab
        slab = blockIdx.z;
        if (slab == 1)      { B = B1; C += (size_t)T_ * D_; }
        else if (slab == 2) { B = B2; C += (size_t)2 * T_ * D_; }
    }
    __shared__ __align__(16) __nv_bfloat16 As[2][BM][HP];
    __shared__ __align__(16) __nv_bfloat16 Bs[2][BN][HP];
    __shared__ __align__(8)  unsigned long long mbarB[2];
    int tid = threadIdx.x;
    int warp = tid >> 5, lane = tid & 31;
    int g = lane >> 2, tg = lane & 3;
    int wm = warp >> 2, wn = warp & 3;
    int m0 = blockIdx.y * BM, n0 = blockIdx.x * BN;

    unsigned mb0 = (unsigned)__cvta_generic_to_shared(&mbarB[0]);
    unsigned mb1 = (unsigned)__cvta_generic_to_shared(&mbarB[1]);
    if (tid == 0) {
        asm volatile("mbarrier.init.shared.b64 [%0], 1;" :: "r"(mb0) : "memory");
        asm volatile("mbarrier.init.shared.b64 [%0], 1;" :: "r"(mb1) : "memory");
        asm volatile("fence.proxy.async.shared::cta;" ::: "memory");
    }
    __syncthreads();

    float acc[4][4][4] = {};
    int nk = K / HKB;

    #define CPA(buf, kt) do {                                                   \
        int k0_ = (kt) * HKB;                                                   \
        _Pragma("unroll")                                                       \
        for (int e = 0; e < 2; e++) {                                           \
            int idx = tid + e * 256;                                            \
            int r_ = idx >> 2, c_ = (idx & 3) * 8;                              \
            const __nv_bfloat16* src_ = A + (size_t)(m0 + r_) * K + k0_ + c_;   \
            unsigned dst_ = (unsigned)__cvta_generic_to_shared(&As[buf][r_][c_]); \
            asm volatile("cp.async.cg.shared.global [%0], [%1], 16;\n"          \
                         :: "r"(dst_), "l"(src_));                              \
        }                                                                       \
    } while (0)
    // one bulk copy: 10240B tiled weight block -> Bs[buf] (exact smem image)
    #define BULKB(buf, kt) do {                                                 \
        if (tid == 0) {                                                         \
            unsigned mb_ = (buf) ? mb1 : mb0;                                   \
            asm volatile("mbarrier.arrive.expect_tx.shared.b64 _, [%0], %1;"    \
                         :: "r"(mb_), "r"(10240u) : "memory");                  \
            unsigned dst_ = (unsigned)__cvta_generic_to_shared(&Bs[buf][0][0]); \
            const __nv_bfloat16* src_ =                                         \
                B + ((size_t)(n0 >> 7) * (K >> 5) + (kt)) * WBLK;               \
            asm volatile("cp.async.bulk.shared::cluster.global"                 \
                         ".mbarrier::complete_tx::bytes [%0], [%1], %2, [%3];"  \
                         :: "r"(dst_), "l"(src_), "r"(10240u), "r"(mb_)         \
                         : "memory");                                           \
        }                                                                       \
    } while (0)

    CPA(0, 0);
    asm volatile("cp.async.commit_group;\n");
    BULKB(0, 0);
    int phB0 = 0, phB1 = 0;

    for (int t = 0; t < nk; t++) {
        int buf = t & 1;
        if (t + 1 < nk) {
            CPA(buf ^ 1, t + 1);
            asm volatile("cp.async.commit_group;\n");
            BULKB(buf ^ 1, t + 1);
            asm volatile("cp.async.wait_group 1;\n");
        } else {
            asm volatile("cp.async.wait_group 0;\n");
        }
        if (buf == 0) { mbar_wait(mb0, phB0); phB0 ^= 1; }
        else          { mbar_wait(mb1, phB1); phB1 ^= 1; }
        __syncthreads();

        #pragma unroll
        for (int ks = 0; ks < 2; ks++) {
            int kb = ks * 16;
            unsigned af[4][4], bfr[4][2];
            #pragma unroll
            for (int i = 0; i < 4; i++) {
                int mr = wm * 64 + i * 16 + g;
                af[i][0] = *(const unsigned*)&As[buf][mr    ][kb + 2 * tg    ];
                af[i][1] = *(const unsigned*)&As[buf][mr + 8][kb + 2 * tg    ];
                af[i][2] = *(const unsigned*)&As[buf][mr    ][kb + 2 * tg + 8];
                af[i][3] = *(const unsigned*)&As[buf][mr + 8][kb + 2 * tg + 8];
            }
            #pragma unroll
            for (int j = 0; j < 4; j++) {
                int nc = wn * 32 + j * 8 + g;
                bfr[j][0] = *(const unsigned*)&Bs[buf][nc][kb + 2 * tg    ];
                bfr[j][1] = *(const unsigned*)&Bs[buf][nc][kb + 2 * tg + 8];
            }
            #pragma unroll
            for (int i = 0; i < 4; i++)
                #pragma unroll
                for (int j = 0; j < 4; j++)
                    MMA_BF16(acc[i][j], af[i][0], af[i][1], af[i][2], af[i][3],
                             bfr[j][0], bfr[j][1]);
        }
        __syncthreads();
    }

    // --- epilogue ---
    #pragma unroll
    for (int i = 0; i < 4; i++) {
        int rbase = m0 + wm * 64 + i * 16 + g;
        #pragma unroll
        for (int j = 0; j < 4; j++) {
            int cbase = n0 + wn * 32 + j * 8 + tg * 2;
            #pragma unroll
            for (int hh = 0; hh < 2; hh++) {
                int rr = rbase + hh * 8;
                #pragma unroll
                for (int cc = 0; cc < 2; cc++) {
                    int nn = cbase + cc;
                    float v = acc[i][j][hh * 2 + cc];
                    if (MODE == EP_HEAD) {
                        int hd = nn >> 6, d = nn & 63;
                        if (slab == 0) {            // q: [h][t][64] fp32
                            C[(size_t)(hd * T_ + rr) * 64 + d] = v;
                        } else if (slab == 1) {     // k: [h][t][64] tf32, col-perm
                            int dp = (d & ~7) + pperm(d & 7);
                            C[(size_t)(hd * T_ + rr) * 64 + dp] =
                                __uint_as_float(cvt_tf32(v));
                        } else {                    // v: [h][64][T] tf32, t-perm
                            int rp = (rr & ~7) + pperm(rr & 7);
                            C[(size_t)(hd * 64 + d) * T_ + rp] =
                                __uint_as_float(cvt_tf32(v));
                        }
                    } else if (MODE == EP_BIASRES) {
                        C[(size_t)rr * N + nn] = v + bias[nn] + res[(size_t)rr * N + nn];
                    } else if (MODE == EP_BIAS) {
                        C[(size_t)rr * N + nn] = v + bias[nn];
                    } else { // EP_SWIGLU
                        float a = aux[(size_t)rr * N + nn];
                        float sig = 1.f / (1.f + __expf(-a));
                        Cb[(size_t)rr * N + nn] = __float2bfloat16((a * sig) * (v + bias[nn]));
                    }
                }
            }
        }
    }
    #undef CPA
    #undef BULKB
}

// ---------------- causal flash attention, tf32 MMA (R14, unchanged) ----------
#define KVP 72

__global__ void __launch_bounds__(256, 2) attn_mma_kernel(
    const float* __restrict__ q, const unsigned* __restrict__ k,
    const unsigned* __restrict__ v, __nv_bfloat16* __restrict__ ctx)
{
    extern __shared__ unsigned smu[];
    unsigned* Ks = smu;                        // [2][64][KVP]
    unsigned* Vs = smu + 2 * 64 * KVP;         // [2][64][KVP]  (rows = d!)
    unsigned* Ps = smu + 4 * 64 * KVP;         // [128][KVP]

    int tid = threadIdx.x;
    int warp = tid >> 5, lane = tid & 31;
    int g = lane >> 2, tg = lane & 3;
    int qt = gridDim.x - 1 - blockIdx.x;       // big tiles first
    int h = blockIdx.y;
    int qm0 = qt * 128;
    const float*    qh = q + (size_t)h * (T_ * HD_);
    const unsigned* kh = k + (size_t)h * (T_ * HD_);
    const unsigned* vh = v + (size_t)h * (T_ * HD_);   // [64][T] layout

    int r0 = qm0 + warp * 16 + g;
    int r1 = r0 + 8;
    int wlast = qm0 + warp * 16 + 15;

    int pa = pperm(2 * tg), pb = pperm(2 * tg + 1);

    unsigned qf[8][4];
    #pragma unroll
    for (int kc = 0; kc < 8; kc++) {
        qf[kc][0] = cvt_tf32(qh[(size_t)r0 * 64 + kc * 8 + tg    ] * 0.125f);
        qf[kc][1] = cvt_tf32(qh[(size_t)r1 * 64 + kc * 8 + tg    ] * 0.125f);
        qf[kc][2] = cvt_tf32(qh[(size_t)r0 * 64 + kc * 8 + tg + 4] * 0.125f);
        qf[kc][3] = cvt_tf32(qh[(size_t)r1 * 64 + kc * 8 + tg + 4] * 0.125f);
    }

    float oacc[8][4] = {};
    float m0 = -1e30f, m1 = -1e30f, l0 = 0.f, l1 = 0.f;
    int nkt = 2 * qt + 2;

    #define CPKV(b, kt) do {                                                    \
        int km_ = (kt) * 64;                                                    \
        _Pragma("unroll")                                                       \
        for (int e = 0; e < 4; e++) {                                           \
            int idx = tid + e * 256;                                            \
            int r_ = idx >> 4, c_ = (idx & 15) * 4;                             \
            unsigned kd_ = (unsigned)__cvta_generic_to_shared(                  \
                &Ks[(b) * 64 * KVP + r_ * KVP + c_]);                           \
            asm volatile("cp.async.cg.shared.global [%0], [%1], 16;\n"          \
                :: "r"(kd_), "l"(kh + (size_t)(km_ + r_) * 64 + c_));           \
            unsigned vd_ = (unsigned)__cvta_generic_to_shared(                  \
                &Vs[(b) * 64 * KVP + r_ * KVP + c_]);                           \
            asm volatile("cp.async.cg.shared.global [%0], [%1], 16;\n"          \
                :: "r"(vd_), "l"(vh + (size_t)r_ * T_ + km_ + c_));             \
        }                                                                       \
    } while (0)

    CPKV(0, 0);
    asm volatile("cp.async.commit_group;\n");

    for (int kt = 0; kt < nkt; kt++) {
        int buf = kt & 1;
        if (kt + 1 < nkt) {
            CPKV(buf ^ 1, kt + 1);
            asm volatile("cp.async.commit_group;\n");
            asm volatile("cp.async.wait_group 1;\n");
        } else {
            asm volatile("cp.async.wait_group 0;\n");
        }
        __syncthreads();
        int km0 = kt * 64;

        if (km0 <= wlast) {
            const unsigned* Kb = Ks + buf * 64 * KVP;
            const unsigned* Vb = Vs + buf * 64 * KVP;

            float sacc[8][4] = {};
            #pragma unroll
            for (int kc = 0; kc < 8; kc++) {
                #pragma unroll
                for (int j = 0; j < 8; j++) {
                    uint2 bb = *(const uint2*)&Kb[(j * 8 + g) * KVP + kc * 8 + 2 * tg];
                    MMA_TF32(sacc[j], qf[kc][0], qf[kc][1], qf[kc][2], qf[kc][3],
                             bb.x, bb.y);
                }
            }

            if (km0 + 63 > qm0 + warp * 16) {
                #pragma unroll
                for (int j = 0; j < 8; j++) {
                    int c0 = km0 + j * 8 + tg * 2, c1 = c0 + 1;
                    if (c0 > r0) sacc[j][0] = -1e30f;
                    if (c1 > r0) sacc[j][1] = -1e30f;
                    if (c0 > r1) sacc[j][2] = -1e30f;
                    if (c1 > r1) sacc[j][3] = -1e30f;
                }
            }

            float t0 = -1e30f, t1 = -1e30f;
            #pragma unroll
            for (int j = 0; j < 8; j++) {
                t0 = fmaxf(t0, fmaxf(sacc[j][0], sacc[j][1]));
                t1 = fmaxf(t1, fmaxf(sacc[j][2], sacc[j][3]));
            }
            t0 = fmaxf(t0, __shfl_xor_sync(0xffffffffu, t0, 1));
            t0 = fmaxf(t0, __shfl_xor_sync(0xffffffffu, t0, 2));
            t1 = fmaxf(t1, __shfl_xor_sync(0xffffffffu, t1, 1));
            t1 = fmaxf(t1, __shfl_xor_sync(0xffffffffu, t1, 2));
            float nm0 = fmaxf(m0, t0), nm1 = fmaxf(m1, t1);
            float rs0 = __expf(m0 - nm0), rs1 = __expf(m1 - nm1);
            m0 = nm0; m1 = nm1;

            int pr0 = (warp * 16 + g) * KVP, pr1 = pr0 + 8 * KVP;
            float sum0 = 0.f, sum1 = 0.f;
            #pragma unroll
            for (int j = 0; j < 8; j++) {
                float p00 = __expf(sacc[j][0] - m0);
                float p01 = __expf(sacc[j][1] - m0);
                float p10 = __expf(sacc[j][2] - m1);
                float p11 = __expf(sacc[j][3] - m1);
                sum0 += p00 + p01; sum1 += p10 + p11;
                Ps[pr0 + j * 8 + pa] = cvt_tf32(p00);
                Ps[pr0 + j * 8 + pb] = cvt_tf32(p01);
                Ps[pr1 + j * 8 + pa] = cvt_tf32(p10);
                Ps[pr1 + j * 8 + pb] = cvt_tf32(p11);
            }
            l0 = l0 * rs0 + sum0;
            l1 = l1 * rs1 + sum1;
            #pragma unroll
            for (int j = 0; j < 8; j++) {
                oacc[j][0] *= rs0; oacc[j][1] *= rs0;
                oacc[j][2] *= rs1; oacc[j][3] *= rs1;
            }
            __syncwarp();

            #pragma unroll
            for (int kc = 0; kc < 8; kc++) {
                uint2 aA = *(const uint2*)&Ps[pr0 + kc * 8 + 2 * tg];
                uint2 aB = *(const uint2*)&Ps[pr1 + kc * 8 + 2 * tg];
                #pragma unroll
                for (int j = 0; j < 8; j++) {
                    uint2 bb = *(const uint2*)&Vb[(j * 8 + g) * KVP + kc * 8 + 2 * tg];
                    MMA_TF32(oacc[j], aA.x, aB.x, aA.y, aB.y, bb.x, bb.y);
                }
            }
            __syncwarp();
        }
        __syncthreads();
    }

    l0 += __shfl_xor_sync(0xffffffffu, l0, 1);
    l0 += __shfl_xor_sync(0xffffffffu, l0, 2);
    l1 += __shfl_xor_sync(0xffffffffu, l1, 1);
    l1 += __shfl_xor_sync(0xffffffffu, l1, 2);
    float inv0 = 1.f / l0, inv1 = 1.f / l1;
    #pragma unroll
    for (int j = 0; j < 8; j++) {
        int col = h * 64 + j * 8 + tg * 2;
        ctx[(size_t)r0 * D_ + col    ] = __float2bfloat16(oacc[j][0] * inv0);
        ctx[(size_t)r0 * D_ + col + 1] = __float2bfloat16(oacc[j][1] * inv0);
        ctx[(size_t)r1 * D_ + col    ] = __float2bfloat16(oacc[j][2] * inv1);
        ctx[(size_t)r1 * D_ + col + 1] = __float2bfloat16(oacc[j][3] * inv1);
    }
    #undef CPKV
}

// ---------------- launch -----------------------------------------------------
extern "C" void kernel_launch(void* const* d_in, const int* in_sizes, int n_in,
                              void* d_out, int out_size) {
    const float* x  = (const float*)d_in[0];
    const float* Wq = (const float*)d_in[1];
    const float* Wk = (const float*)d_in[2];
    const float* Wv = (const float*)d_in[3];
    const float* Wo = (const float*)d_in[4];
    const float* bo = (const float*)d_in[5];
    const float* w1 = (const float*)d_in[6];
    const float* b1 = (const float*)d_in[7];
    const float* w2 = (const float*)d_in[8];
    const float* b2 = (const float*)d_in[9];
    const float* w3 = (const float*)d_in[10];
    const float* b3 = (const float*)d_in[11];
    const float* g1 = (const float*)d_in[12];
    const float* s1 = (const float*)d_in[13];
    const float* g2 = (const float*)d_in[14];
    const float* s2 = (const float*)d_in[15];
    float* out = (float*)d_out;

    __nv_bfloat16 *hb, *ctxb, *ffb, *Wqb, *Wkb, *Wvb, *Wob, *w1b, *w2b, *w3b;
    float *qkvb, *x2b, *y1b;
    cudaGetSymbolAddress((void**)&hb,   g_hb);
    cudaGetSymbolAddress((void**)&qkvb, g_qkv);
    cudaGetSymbolAddress((void**)&ctxb, g_ctxb);
    cudaGetSymbolAddress((void**)&x2b,  g_x2);
    cudaGetSymbolAddress((void**)&y1b,  g_y1);
    cudaGetSymbolAddress((void**)&ffb,  g_ffb);
    cudaGetSymbolAddress((void**)&Wqb,  g_Wqb);
    cudaGetSymbolAddress((void**)&Wkb,  g_Wkb);
    cudaGetSymbolAddress((void**)&Wvb,  g_Wvb);
    cudaGetSymbolAddress((void**)&Wob,  g_Wob);
    cudaGetSymbolAddress((void**)&w1b,  g_w1b);
    cudaGetSymbolAddress((void**)&w2b,  g_w2b);
    cudaGetSymbolAddress((void**)&w3b,  g_w3b);

    const int attn_smem = (4 * 64 * KVP + 128 * KVP) * (int)sizeof(unsigned);
    cudaFuncSetAttribute(attn_mma_kernel, cudaFuncAttributeMaxDynamicSharedMemorySize, attn_smem);

    // weight prepass: convert + transpose + tile, ONE launch
    wconv_all_kernel<<<9216, dim3(32, 8)>>>(Wq, Wk, Wv, Wo, w1, w2, w3);

    dim3 gD(D_ / BN, T_ / BM);        // (6, 32)
    dim3 gQKV(D_ / BN, T_ / BM, 3);   // fused QKV
    dim3 gF(FF_ / BN, T_ / BM);       // (24, 32)

    // 1. LN1 (bf16 out)
    ln_kernel<<<T_, 256>>>(x, g1, s1, hb);
    // 2. fused QKV projections (q fp32; k col-perm tf32; v transposed tf32)
    bf16_gemm<EP_HEAD><<<gQKV, 256>>>(hb, Wqb, Wkb, Wvb, nullptr, nullptr, nullptr,
                                      qkvb, nullptr, D_, D_);
    // 3. causal attention (tf32 MMA; bf16 ctx out)
    attn_mma_kernel<<<dim3(T_ / 128, H_), 256, attn_smem>>>(
        qkvb, (const unsigned*)(qkvb + (size_t)T_ * D_),
        (const unsigned*)(qkvb + (size_t)2 * T_ * D_), ctxb);
    // 4. out projection + bias + residual (fp32 out)
    bf16_gemm<EP_BIASRES><<<gD, 256>>>(ctxb, Wob, nullptr, nullptr, bo, x, nullptr,
                                       x2b, nullptr, D_, D_);
    // 5. LN2 (bf16 out)
    ln_kernel<<<T_, 256>>>(x2b, g2, s2, hb);
    // 6. SwiGLU: y1 = h@w1+b1 (fp32) ; ff = silu(y1) * (h@w2+b2) (bf16)
    bf16_gemm<EP_BIAS>  <<<gF, 256>>>(hb, w1b, nullptr, nullptr, b1, nullptr, nullptr,
                                      y1b, nullptr, FF_, D_);
    bf16_gemm<EP_SWIGLU><<<gF, 256>>>(hb, w2b, nullptr, nullptr, b2, nullptr, y1b,
                                      nullptr, ffb, FF_, D_);
    // 7. down projection + bias + residual -> output (fp32)
    bf16_gemm<EP_BIASRES><<<gD, 256>>>(ffb, w3b, nullptr, nullptr, b3, x2b, nullptr,
                                       out, nullptr, D_, FF_);
}